// round 2
// baseline (speedup 1.0000x reference)
#include <cuda_runtime.h>
#include <cuda_bf16.h>
#include <mma.h>
#include <math.h>

using namespace nvcuda;

#define BQ   2
#define LQ   1024
#define DM   1024
#define DI   2048
#define DS   16
#define NROW (BQ*LQ)      // 2048
#define NC   8            // chunks
#define TCH  (LQ/NC)      // 128 steps per chunk
#define WXN  128          // padded N for the W_x gemm

// ---------------- scratch (__device__ globals; no allocs allowed) ----------------
__device__ __nv_bfloat16 g_xn[NROW*DM];            // layernorm out (bf16)
__device__ __nv_bfloat16 g_Win[DM*2*DI];           // W_in bf16
__device__ __nv_bfloat16 g_Wout[DI*DM];            // W_out bf16
__device__ __nv_bfloat16 g_Wx[DI*WXN];             // W_x bf16 padded to 128 cols
__device__ float         g_xz[(size_t)NROW*2*DI];  // gemm1 out: [:,0:2048]=x_ssm, [:,2048:]=z
__device__ float         g_xc[(size_t)NROW*DI];    // conv+silu out fp32
__device__ __nv_bfloat16 g_xcb[(size_t)NROW*DI];   // conv+silu out bf16
__device__ float         g_xpraw[NROW*WXN];        // xp gemm out (padded)
__device__ float         g_xpp[NROW*36];           // per (b,l): [0:16]=delta*B, [16:32]=C, [32]=delta
__device__ float         g_y[(size_t)NROW*DI];     // scan output
__device__ __nv_bfloat16 g_g[(size_t)NROW*DI];     // gated bf16 (gemm2 A)
__device__ float         g_ot[(size_t)NROW*DM];    // gemm2 out
__device__ float         g_hfin[BQ*NC*DI*DS];      // per-chunk local final states
__device__ float         g_h0[BQ*NC*DI*DS];        // true chunk-entry states
__device__ float         g_S[BQ*NC];               // per-chunk delta sums

// ---------------- weight converts ----------------
__global__ void cvt_win_k(const float* __restrict__ w) {
    int i = blockIdx.x*256 + threadIdx.x;
    if (i < DM*2*DI) g_Win[i] = __float2bfloat16(w[i]);
}
__global__ void cvt_wout_k(const float* __restrict__ w) {
    int i = blockIdx.x*256 + threadIdx.x;
    if (i < DI*DM) g_Wout[i] = __float2bfloat16(w[i]);
}
__global__ void cvt_wx_k(const float* __restrict__ w) {
    int i = blockIdx.x*256 + threadIdx.x;
    if (i < DI*WXN) {
        int k = i >> 7, n = i & (WXN-1);
        g_Wx[i] = __float2bfloat16(n < (2*DS+1) ? w[k*(2*DS+1) + n] : 0.f);
    }
}

// ---------------- layernorm (block per row, bf16 out) ----------------
__global__ void ln_k(const float* __restrict__ x, const float* __restrict__ w,
                     const float* __restrict__ b) {
    __shared__ float red[8];
    __shared__ float bcast;
    int r = blockIdx.x, tid = threadIdx.x;
    const float* xr = x + (size_t)r*DM;
    float v0 = xr[tid], v1 = xr[tid+256], v2 = xr[tid+512], v3 = xr[tid+768];
    float s = v0+v1+v2+v3;
    #pragma unroll
    for (int o=16;o;o>>=1) s += __shfl_xor_sync(0xffffffffu, s, o);
    if ((tid&31)==0) red[tid>>5] = s;
    __syncthreads();
    if (tid==0) {
        float t = red[0]+red[1]+red[2]+red[3]+red[4]+red[5]+red[6]+red[7];
        bcast = t*(1.f/DM);
    }
    __syncthreads();
    float mu = bcast;
    float d0=v0-mu, d1=v1-mu, d2=v2-mu, d3=v3-mu;
    float q = d0*d0+d1*d1+d2*d2+d3*d3;
    __syncthreads();
    #pragma unroll
    for (int o=16;o;o>>=1) q += __shfl_xor_sync(0xffffffffu, q, o);
    if ((tid&31)==0) red[tid>>5] = q;
    __syncthreads();
    if (tid==0) {
        float t = red[0]+red[1]+red[2]+red[3]+red[4]+red[5]+red[6]+red[7];
        bcast = rsqrtf(t*(1.f/DM) + 1e-5f);
    }
    __syncthreads();
    float inv = bcast;
    __nv_bfloat16* o = g_xn + (size_t)r*DM;
    o[tid    ] = __float2bfloat16(d0*inv*w[tid    ] + b[tid    ]);
    o[tid+256] = __float2bfloat16(d1*inv*w[tid+256] + b[tid+256]);
    o[tid+512] = __float2bfloat16(d2*inv*w[tid+512] + b[tid+512]);
    o[tid+768] = __float2bfloat16(d3*inv*w[tid+768] + b[tid+768]);
}

// ---------------- generic bf16 wmma GEMM: C[M,N] = A[M,K] @ B[K,N], fp32 accum ----------------
#define BM 128
#define BN 128
#define BK 32
__global__ void __launch_bounds__(256) gemm_k(const __nv_bfloat16* __restrict__ A,
                                              const __nv_bfloat16* __restrict__ B,
                                              float* __restrict__ C,
                                              int N, int K) {
    __shared__ __align__(16) __nv_bfloat16 As[BM][BK+8];
    __shared__ __align__(16) __nv_bfloat16 Bs[BK][BN+8];
    int bx = blockIdx.x, by = blockIdx.y;
    int tid = threadIdx.x;
    int warp = tid >> 5;
    int wm = warp & 3;        // 4 warps in M (32 rows each -> 2 frags)
    int wn = warp >> 2;       // 2 warps in N (64 cols each -> 4 frags)

    wmma::fragment<wmma::accumulator,16,16,16,float> acc[2][4];
    #pragma unroll
    for (int i=0;i<2;i++)
        #pragma unroll
        for (int j=0;j<4;j++) wmma::fill_fragment(acc[i][j], 0.f);

    for (int k0=0; k0<K; k0+=BK) {
        #pragma unroll
        for (int t=tid; t<BM*BK/8; t+=256) {            // 512 uint4
            int row = t >> 2, c8 = t & 3;
            *(uint4*)&As[row][c8*8] = *(const uint4*)&A[(size_t)(by*BM+row)*K + k0 + c8*8];
        }
        #pragma unroll
        for (int t=tid; t<BK*BN/8; t+=256) {            // 512 uint4
            int row = t >> 4, c8 = t & 15;
            *(uint4*)&Bs[row][c8*8] = *(const uint4*)&B[(size_t)(k0+row)*N + bx*BN + c8*8];
        }
        __syncthreads();
        #pragma unroll
        for (int kk=0; kk<BK; kk+=16) {
            wmma::fragment<wmma::matrix_a,16,16,16,__nv_bfloat16,wmma::row_major> af[2];
            wmma::fragment<wmma::matrix_b,16,16,16,__nv_bfloat16,wmma::row_major> bf[4];
            #pragma unroll
            for (int i=0;i<2;i++) wmma::load_matrix_sync(af[i], &As[wm*32+i*16][kk], BK+8);
            #pragma unroll
            for (int j=0;j<4;j++) wmma::load_matrix_sync(bf[j], &Bs[kk][wn*64+j*16], BN+8);
            #pragma unroll
            for (int i=0;i<2;i++)
                #pragma unroll
                for (int j=0;j<4;j++) wmma::mma_sync(acc[i][j], af[i], bf[j], acc[i][j]);
        }
        __syncthreads();
    }
    #pragma unroll
    for (int i=0;i<2;i++)
        #pragma unroll
        for (int j=0;j<4;j++)
            wmma::store_matrix_sync(&C[(size_t)(by*BM+wm*32+i*16)*N + bx*BN+wn*64+j*16],
                                    acc[i][j], N, wmma::mem_row_major);
}

// ---------------- depthwise causal conv (k=4) + silu ----------------
__global__ void conv_k(const float* __restrict__ cw, const float* __restrict__ cb) {
    int d = blockIdx.x*256 + threadIdx.x;
    int r = blockIdx.y;
    int l = r & (LQ-1);
    float acc = cb[d];
    float w0 = cw[d*4+0], w1 = cw[d*4+1], w2 = cw[d*4+2], w3 = cw[d*4+3];
    const float* base = g_xz + (size_t)r*(2*DI) + d;
    if (l >= 3) acc = fmaf(base[-3*2*DI], w0, acc);
    if (l >= 2) acc = fmaf(base[-2*2*DI], w1, acc);
    if (l >= 1) acc = fmaf(base[-1*2*DI], w2, acc);
    acc = fmaf(base[0], w3, acc);
    float sv = acc / (1.f + __expf(-acc));
    g_xc[(size_t)r*DI + d]  = sv;
    g_xcb[(size_t)r*DI + d] = __float2bfloat16(sv);
}

// ---------------- xp postprocess: softplus(delta), fold delta into B ----------------
__global__ void xpost_k() {
    __shared__ float sd;
    int r = blockIdx.x, tid = threadIdx.x;
    float v = 0.f;
    if (tid < 33) v = g_xpraw[r*WXN + tid];
    if (tid == 32) {
        float dl = (v > 20.f) ? v : log1pf(__expf(v));
        sd = dl;
        g_xpp[r*36 + 32] = dl;
    }
    __syncthreads();
    if (tid < 16)       g_xpp[r*36 + tid] = v * sd;   // delta * B_n
    else if (tid < 32)  g_xpp[r*36 + tid] = v;        // C_n
}

// ---------------- per-chunk delta sums ----------------
__global__ void sums_k() {
    __shared__ float red[4];
    int bc = blockIdx.x, t = threadIdx.x;      // 16 blocks x 128 threads
    int b = bc >> 3, c = bc & 7;
    float v = g_xpp[(size_t)((b*LQ + c*TCH + t))*36 + 32];
    #pragma unroll
    for (int o=16;o;o>>=1) v += __shfl_xor_sync(0xffffffffu, v, o);
    if ((t&31)==0) red[t>>5] = v;
    __syncthreads();
    if (t==0) g_S[bc] = red[0]+red[1]+red[2]+red[3];
}

// ---------------- scan pass A: local chunk scans, h_init = 0 ----------------
__global__ void __launch_bounds__(256) scanA_k(const float* __restrict__ logA,
                                               const float* __restrict__ Dp) {
    int d = blockIdx.x*256 + threadIdx.x;
    int b = blockIdx.y, c = blockIdx.z;
    float An[DS], h[DS];
    #pragma unroll
    for (int n=0;n<DS;n++) { An[n] = -__expf(logA[d*DS+n]); h[n] = 0.f; }
    float Dd = Dp[d];
    int rbase = b*LQ + c*TCH;
    for (int t=0; t<TCH; t++) {
        int r = rbase + t;
        const float4* p4 = (const float4*)(g_xpp + (size_t)r*36);
        float4 a0 = __ldg(p4+0), a1 = __ldg(p4+1), a2 = __ldg(p4+2), a3 = __ldg(p4+3);
        float4 c0 = __ldg(p4+4), c1 = __ldg(p4+5), c2 = __ldg(p4+6), c3 = __ldg(p4+7);
        float delta = __ldg(g_xpp + (size_t)r*36 + 32);
        float dB[DS], Cc[DS];
        dB[0]=a0.x; dB[1]=a0.y; dB[2]=a0.z; dB[3]=a0.w;
        dB[4]=a1.x; dB[5]=a1.y; dB[6]=a1.z; dB[7]=a1.w;
        dB[8]=a2.x; dB[9]=a2.y; dB[10]=a2.z; dB[11]=a2.w;
        dB[12]=a3.x; dB[13]=a3.y; dB[14]=a3.z; dB[15]=a3.w;
        Cc[0]=c0.x; Cc[1]=c0.y; Cc[2]=c0.z; Cc[3]=c0.w;
        Cc[4]=c1.x; Cc[5]=c1.y; Cc[6]=c1.z; Cc[7]=c1.w;
        Cc[8]=c2.x; Cc[9]=c2.y; Cc[10]=c2.z; Cc[11]=c2.w;
        Cc[12]=c3.x; Cc[13]=c3.y; Cc[14]=c3.z; Cc[15]=c3.w;
        float xv = g_xc[(size_t)r*DI + d];
        float y  = Dd * xv;
        #pragma unroll
        for (int n=0;n<DS;n++) {
            float dA = __expf(delta * An[n]);
            h[n] = fmaf(dA, h[n], dB[n]*xv);
            y    = fmaf(h[n], Cc[n], y);
        }
        g_y[(size_t)r*DI + d] = y;
    }
    float* hf = g_hfin + ((size_t)(b*NC+c)*DI + d)*DS;
    #pragma unroll
    for (int n=0;n<DS;n++) hf[n] = h[n];
}

// ---------------- scan pass B: propagate chunk-entry states ----------------
__global__ void scanB_k(const float* __restrict__ logA, const float* __restrict__ init_state) {
    int idx = blockIdx.x*256 + threadIdx.x;    // BQ*DI*DS = 65536
    int n = idx & 15;
    int d = (idx >> 4) & (DI-1);
    int b = idx >> 15;
    float An = -__expf(logA[d*DS+n]);
    float h0 = init_state[idx];                // [b][d][n] layout matches idx
    #pragma unroll
    for (int c=0;c<NC;c++) {
        g_h0[((size_t)(b*NC+c)*DI + d)*DS + n] = h0;
        float P = __expf(An * g_S[b*NC+c]);
        h0 = fmaf(P, h0, g_hfin[((size_t)(b*NC+c)*DI + d)*DS + n]);
    }
}

// ---------------- scan pass C: decay the true entry state, add correction ----------------
__global__ void __launch_bounds__(256) scanC_k(const float* __restrict__ logA) {
    int d = blockIdx.x*256 + threadIdx.x;
    int b = blockIdx.y, c = blockIdx.z;
    float An[DS], hc[DS];
    const float* h0p = g_h0 + ((size_t)(b*NC+c)*DI + d)*DS;
    float ss = 0.f;
    #pragma unroll
    for (int n=0;n<DS;n++) {
        An[n] = -__expf(logA[d*DS+n]);
        hc[n] = h0p[n];
        ss += fabsf(hc[n]);
    }
    if (__all_sync(0xffffffffu, ss < 1e-30f)) return;
    int rbase = b*LQ + c*TCH;
    for (int t=0; t<TCH; t++) {
        int r = rbase + t;
        const float4* p4 = (const float4*)(g_xpp + (size_t)r*36);
        float4 c0 = __ldg(p4+4), c1 = __ldg(p4+5), c2 = __ldg(p4+6), c3 = __ldg(p4+7);
        float delta = __ldg(g_xpp + (size_t)r*36 + 32);
        float Cc[DS];
        Cc[0]=c0.x; Cc[1]=c0.y; Cc[2]=c0.z; Cc[3]=c0.w;
        Cc[4]=c1.x; Cc[5]=c1.y; Cc[6]=c1.z; Cc[7]=c1.w;
        Cc[8]=c2.x; Cc[9]=c2.y; Cc[10]=c2.z; Cc[11]=c2.w;
        Cc[12]=c3.x; Cc[13]=c3.y; Cc[14]=c3.z; Cc[15]=c3.w;
        float y = 0.f; ss = 0.f;
        #pragma unroll
        for (int n=0;n<DS;n++) {
            hc[n] *= __expf(delta * An[n]);
            y  = fmaf(hc[n], Cc[n], y);
            ss += fabsf(hc[n]);
        }
        g_y[(size_t)r*DI + d] += y;
        if (__all_sync(0xffffffffu, ss < 1e-28f)) break;   // states fully decayed
    }
}

// ---------------- gate: g = y * silu(z), bf16 ----------------
__global__ void gate_k() {
    int i = blockIdx.x*256 + threadIdx.x;
    if (i < NROW*DI) {
        int r = i >> 11, dc = i & (DI-1);
        float z  = g_xz[(size_t)r*(2*DI) + DI + dc];
        float sz = z / (1.f + __expf(-z));
        g_g[i] = __float2bfloat16(g_y[i] * sz);
    }
}

// ---------------- residual add ----------------
__global__ void resid_k(const float* __restrict__ x, float* __restrict__ out) {
    int i = blockIdx.x*256 + threadIdx.x;
    if (i < NROW*DM) out[i] = x[i] + g_ot[i];
}

// ---------------- launch ----------------
extern "C" void kernel_launch(void* const* d_in, const int* in_sizes, int n_in,
                              void* d_out, int out_size) {
    const float* x          = (const float*)d_in[0];
    const float* init_state = (const float*)d_in[1];
    const float* ln_w       = (const float*)d_in[2];
    const float* ln_b       = (const float*)d_in[3];
    const float* W_in       = (const float*)d_in[4];
    const float* conv_w     = (const float*)d_in[5];
    const float* conv_b     = (const float*)d_in[6];
    const float* W_x        = (const float*)d_in[7];
    const float* log_A      = (const float*)d_in[8];
    const float* D_param    = (const float*)d_in[9];
    const float* W_out      = (const float*)d_in[10];
    float* out = (float*)d_out;

    void *p_xn, *p_Win, *p_Wout, *p_Wx, *p_xz, *p_xcb, *p_xpraw, *p_g, *p_ot;
    cudaGetSymbolAddress(&p_xn,    g_xn);
    cudaGetSymbolAddress(&p_Win,   g_Win);
    cudaGetSymbolAddress(&p_Wout,  g_Wout);
    cudaGetSymbolAddress(&p_Wx,    g_Wx);
    cudaGetSymbolAddress(&p_xz,    g_xz);
    cudaGetSymbolAddress(&p_xcb,   g_xcb);
    cudaGetSymbolAddress(&p_xpraw, g_xpraw);
    cudaGetSymbolAddress(&p_g,     g_g);
    cudaGetSymbolAddress(&p_ot,    g_ot);

    cvt_win_k <<<(DM*2*DI+255)/256, 256>>>(W_in);
    cvt_wout_k<<<(DI*DM+255)/256,   256>>>(W_out);
    cvt_wx_k  <<<(DI*WXN+255)/256,  256>>>(W_x);

    ln_k<<<NROW, 256>>>(x, ln_w, ln_b);

    // GEMM1: xz[2048,4096] = xn[2048,1024] @ W_in[1024,4096]
    gemm_k<<<dim3(2*DI/BN, NROW/BM), 256>>>((const __nv_bfloat16*)p_xn,
                                            (const __nv_bfloat16*)p_Win,
                                            (float*)p_xz, 2*DI, DM);

    conv_k<<<dim3(DI/256, NROW), 256>>>(conv_w, conv_b);

    // xp GEMM: [2048,128] = xconv[2048,2048] @ Wx[2048,128]
    gemm_k<<<dim3(WXN/BN, NROW/BM), 256>>>((const __nv_bfloat16*)p_xcb,
                                           (const __nv_bfloat16*)p_Wx,
                                           (float*)p_xpraw, WXN, DI);

    xpost_k<<<NROW, 64>>>();
    sums_k<<<BQ*NC, TCH>>>();

    scanA_k<<<dim3(DI/256, BQ, NC), 256>>>(log_A, D_param);
    scanB_k<<<(BQ*DI*DS)/256, 256>>>(log_A, init_state);
    scanC_k<<<dim3(DI/256, BQ, NC), 256>>>(log_A);

    gate_k<<<(NROW*DI)/256, 256>>>();

    // GEMM2: ot[2048,1024] = g[2048,2048] @ W_out[2048,1024]
    gemm_k<<<dim3(DM/BN, NROW/BM), 256>>>((const __nv_bfloat16*)p_g,
                                          (const __nv_bfloat16*)p_Wout,
                                          (float*)p_ot, DM, DI);

    resid_k<<<(NROW*DM)/256, 256>>>(x, out);
}

// round 4
// speedup vs baseline: 1.2173x; 1.2173x over previous
#include <cuda_runtime.h>
#include <cuda_bf16.h>
#include <mma.h>
#include <math.h>
#include <stdint.h>

using namespace nvcuda;

#define BQ   2
#define LQ   1024
#define DM   1024
#define DI   2048
#define DS   16
#define NROW (BQ*LQ)      // 2048
#define NC   8            // chunks
#define TCH  (LQ/NC)      // 128 steps per chunk
#define WXN  128          // padded N for the W_x gemm
#define KSPL 8            // split-K factor for xp gemm

// ---------------- scratch (__device__ globals; no allocs allowed) ----------------
__device__ __nv_bfloat16 g_xn[NROW*DM];            // layernorm out (bf16)
__device__ __nv_bfloat16 g_Win[DM*2*DI];           // W_in bf16
__device__ __nv_bfloat16 g_Wout[DI*DM];            // W_out bf16
__device__ __nv_bfloat16 g_Wx[DI*WXN];             // W_x bf16 padded to 128 cols
__device__ float         g_xz[(size_t)NROW*2*DI];  // gemm1 out: [:,0:2048]=x_ssm, [:,2048:]=z
__device__ float         g_xc[(size_t)NROW*DI];    // conv+silu out fp32
__device__ __nv_bfloat16 g_xcb[(size_t)NROW*DI];   // conv+silu out bf16
__device__ float         g_xpraw[(size_t)KSPL*NROW*WXN]; // xp gemm split-K partials
__device__ float         g_xpp[NROW*36];           // per (b,l): [0:16]=delta*B, [16:32]=C, [32]=delta
__device__ float         g_y[(size_t)NROW*DI];     // scan output
__device__ __nv_bfloat16 g_g[(size_t)NROW*DI];     // gated bf16 (gemm2 A)
__device__ float         g_ot[(size_t)NROW*DM];    // gemm2 out
__device__ float         g_hfin[BQ*NC*DI*DS];      // per-chunk local final states
__device__ float         g_h0[BQ*NC*DI*DS];        // true chunk-entry states
__device__ float         g_S[BQ*NC];               // per-chunk delta sums

// ---------------- weight converts ----------------
__global__ void cvt_win_k(const float* __restrict__ w) {
    int i = blockIdx.x*256 + threadIdx.x;
    if (i < DM*2*DI) g_Win[i] = __float2bfloat16(w[i]);
}
__global__ void cvt_wout_k(const float* __restrict__ w) {
    int i = blockIdx.x*256 + threadIdx.x;
    if (i < DI*DM) g_Wout[i] = __float2bfloat16(w[i]);
}
__global__ void cvt_wx_k(const float* __restrict__ w) {
    int i = blockIdx.x*256 + threadIdx.x;
    if (i < DI*WXN) {
        int k = i >> 7, n = i & (WXN-1);
        g_Wx[i] = __float2bfloat16(n < (2*DS+1) ? w[k*(2*DS+1) + n] : 0.f);
    }
}

// ---------------- layernorm (block per row, bf16 out) ----------------
__global__ void ln_k(const float* __restrict__ x, const float* __restrict__ w,
                     const float* __restrict__ b) {
    __shared__ float red[8];
    __shared__ float bcast;
    int r = blockIdx.x, tid = threadIdx.x;
    const float* xr = x + (size_t)r*DM;
    float v0 = xr[tid], v1 = xr[tid+256], v2 = xr[tid+512], v3 = xr[tid+768];
    float s = v0+v1+v2+v3;
    #pragma unroll
    for (int o=16;o;o>>=1) s += __shfl_xor_sync(0xffffffffu, s, o);
    if ((tid&31)==0) red[tid>>5] = s;
    __syncthreads();
    if (tid==0) {
        float t = red[0]+red[1]+red[2]+red[3]+red[4]+red[5]+red[6]+red[7];
        bcast = t*(1.f/DM);
    }
    __syncthreads();
    float mu = bcast;
    float d0=v0-mu, d1=v1-mu, d2=v2-mu, d3=v3-mu;
    float q = d0*d0+d1*d1+d2*d2+d3*d3;
    __syncthreads();
    #pragma unroll
    for (int o=16;o;o>>=1) q += __shfl_xor_sync(0xffffffffu, q, o);
    if ((tid&31)==0) red[tid>>5] = q;
    __syncthreads();
    if (tid==0) {
        float t = red[0]+red[1]+red[2]+red[3]+red[4]+red[5]+red[6]+red[7];
        bcast = rsqrtf(t*(1.f/DM) + 1e-5f);
    }
    __syncthreads();
    float inv = bcast;
    __nv_bfloat16* o = g_xn + (size_t)r*DM;
    o[tid    ] = __float2bfloat16(d0*inv*w[tid    ] + b[tid    ]);
    o[tid+256] = __float2bfloat16(d1*inv*w[tid+256] + b[tid+256]);
    o[tid+512] = __float2bfloat16(d2*inv*w[tid+512] + b[tid+512]);
    o[tid+768] = __float2bfloat16(d3*inv*w[tid+768] + b[tid+768]);
}

// ---------------- pipelined bf16 wmma GEMM with cp.async double buffering ----------------
// C[M,N] = A[M,K-slice] @ B[K-slice,N]; slice = [bz*kchunk, (bz+1)*kchunk); C += bz*cstride
#define BM 128
#define BN 128
#define BK 32
#define APAD 16
#define BPAD 16

__device__ __forceinline__ void cpa16(void* dst_smem, const void* src_gmem) {
    unsigned d = (unsigned)__cvta_generic_to_shared(dst_smem);
    asm volatile("cp.async.cg.shared.global [%0], [%1], 16;" :: "r"(d), "l"(src_gmem));
}

__global__ void __launch_bounds__(256) gemm_k(const __nv_bfloat16* __restrict__ A,
                                              const __nv_bfloat16* __restrict__ B,
                                              float* __restrict__ C,
                                              int N, int K, int kchunk, size_t cstride) {
    __shared__ __align__(16) __nv_bfloat16 As[2][BM][BK+APAD];
    __shared__ __align__(16) __nv_bfloat16 Bs[2][BK][BN+BPAD];
    int bx = blockIdx.x, by = blockIdx.y, bz = blockIdx.z;
    int tid = threadIdx.x;
    int warp = tid >> 5;
    int wm = warp & 3;        // 4 warps in M (32 rows each -> 2 frags)
    int wn = warp >> 2;       // 2 warps in N (64 cols each -> 4 frags)
    int kbeg = bz * kchunk;
    C += (size_t)bz * cstride;

    wmma::fragment<wmma::accumulator,16,16,16,float> acc[2][4];
    #pragma unroll
    for (int i=0;i<2;i++)
        #pragma unroll
        for (int j=0;j<4;j++) wmma::fill_fragment(acc[i][j], 0.f);

    // per-thread copy coordinates
    // A tile: 128 rows x 32 cols bf16 = 512 x 16B  -> 2 chunks/thread
    int a_row0 = (tid      ) >> 2, a_ch0 = (tid      ) & 3;
    int a_row1 = (tid + 256) >> 2, a_ch1 = (tid + 256) & 3;
    // B tile: 32 rows x 128 cols bf16 = 512 x 16B -> 2 chunks/thread
    int b_row0 = (tid      ) >> 4, b_ch0 = (tid      ) & 15;
    int b_row1 = (tid + 256) >> 4, b_ch1 = (tid + 256) & 15;

    const __nv_bfloat16* Abase = A + (size_t)(by*BM)*K + kbeg;
    const __nv_bfloat16* Bbase = B + (size_t)kbeg*N + bx*BN;

    auto load_tile = [&](int s, int koff) {
        cpa16(&As[s][a_row0][a_ch0*8], Abase + (size_t)a_row0*K + koff + a_ch0*8);
        cpa16(&As[s][a_row1][a_ch1*8], Abase + (size_t)a_row1*K + koff + a_ch1*8);
        cpa16(&Bs[s][b_row0][b_ch0*8], Bbase + (size_t)(koff+b_row0)*N + b_ch0*8);
        cpa16(&Bs[s][b_row1][b_ch1*8], Bbase + (size_t)(koff+b_row1)*N + b_ch1*8);
        asm volatile("cp.async.commit_group;");
    };

    int ntiles = kchunk / BK;
    load_tile(0, 0);

    for (int it = 0; it < ntiles; it++) {
        if (it + 1 < ntiles) {
            load_tile((it+1)&1, (it+1)*BK);
            asm volatile("cp.async.wait_group 1;");
        } else {
            asm volatile("cp.async.wait_group 0;");
        }
        __syncthreads();
        int s = it & 1;
        #pragma unroll
        for (int kk=0; kk<BK; kk+=16) {
            wmma::fragment<wmma::matrix_a,16,16,16,__nv_bfloat16,wmma::row_major> af[2];
            wmma::fragment<wmma::matrix_b,16,16,16,__nv_bfloat16,wmma::row_major> bf[4];
            #pragma unroll
            for (int i=0;i<2;i++) wmma::load_matrix_sync(af[i], &As[s][wm*32+i*16][kk], BK+APAD);
            #pragma unroll
            for (int j=0;j<4;j++) wmma::load_matrix_sync(bf[j], &Bs[s][kk][wn*64+j*16], BN+BPAD);
            #pragma unroll
            for (int i=0;i<2;i++)
                #pragma unroll
                for (int j=0;j<4;j++) wmma::mma_sync(acc[i][j], af[i], bf[j], acc[i][j]);
        }
        __syncthreads();
    }

    #pragma unroll
    for (int i=0;i<2;i++)
        #pragma unroll
        for (int j=0;j<4;j++)
            wmma::store_matrix_sync(&C[(size_t)(by*BM+wm*32+i*16)*N + bx*BN+wn*64+j*16],
                                    acc[i][j], N, wmma::mem_row_major);
}

// ---------------- depthwise causal conv (k=4) + silu ----------------
__global__ void conv_k(const float* __restrict__ cw, const float* __restrict__ cb) {
    int d = blockIdx.x*256 + threadIdx.x;
    int r = blockIdx.y;
    int l = r & (LQ-1);
    float acc = cb[d];
    float w0 = cw[d*4+0], w1 = cw[d*4+1], w2 = cw[d*4+2], w3 = cw[d*4+3];
    const float* base = g_xz + (size_t)r*(2*DI) + d;
    if (l >= 3) acc = fmaf(base[-3*2*DI], w0, acc);
    if (l >= 2) acc = fmaf(base[-2*2*DI], w1, acc);
    if (l >= 1) acc = fmaf(base[-1*2*DI], w2, acc);
    acc = fmaf(base[0], w3, acc);
    float sv = acc / (1.f + __expf(-acc));
    g_xc[(size_t)r*DI + d]  = sv;
    g_xcb[(size_t)r*DI + d] = __float2bfloat16(sv);
}

// ---------------- xp postprocess: sum split-K partials, softplus(delta), fold delta into B ----------------
__global__ void xpost_k() {
    __shared__ float sd;
    int r = blockIdx.x, tid = threadIdx.x;
    float v = 0.f;
    if (tid < 33) {
        #pragma unroll
        for (int s=0; s<KSPL; s++)
            v += g_xpraw[(size_t)s*NROW*WXN + r*WXN + tid];
    }
    if (tid == 32) {
        float dl = (v > 20.f) ? v : log1pf(__expf(v));
        sd = dl;
        g_xpp[r*36 + 32] = dl;
    }
    __syncthreads();
    if (tid < 16)       g_xpp[r*36 + tid] = v * sd;   // delta * B_n
    else if (tid < 32)  g_xpp[r*36 + tid] = v;        // C_n
}

// ---------------- per-chunk delta sums ----------------
__global__ void sums_k() {
    __shared__ float red[4];
    int bc = blockIdx.x, t = threadIdx.x;      // 16 blocks x 128 threads
    int b = bc >> 3, c = bc & 7;
    float v = g_xpp[(size_t)((b*LQ + c*TCH + t))*36 + 32];
    #pragma unroll
    for (int o=16;o;o>>=1) v += __shfl_xor_sync(0xffffffffu, v, o);
    if ((t&31)==0) red[t>>5] = v;
    __syncthreads();
    if (t==0) g_S[bc] = red[0]+red[1]+red[2]+red[3];
}

// ---------------- scan pass A: local chunk scans, h_init = 0 ----------------
__global__ void __launch_bounds__(256) scanA_k(const float* __restrict__ logA,
                                               const float* __restrict__ Dp) {
    int d = blockIdx.x*256 + threadIdx.x;
    int b = blockIdx.y, c = blockIdx.z;
    float An[DS], h[DS];
    #pragma unroll
    for (int n=0;n<DS;n++) { An[n] = -__expf(logA[d*DS+n]); h[n] = 0.f; }
    float Dd = Dp[d];
    int rbase = b*LQ + c*TCH;
    for (int t=0; t<TCH; t++) {
        int r = rbase + t;
        const float4* p4 = (const float4*)(g_xpp + (size_t)r*36);
        float4 a0 = __ldg(p4+0), a1 = __ldg(p4+1), a2 = __ldg(p4+2), a3 = __ldg(p4+3);
        float4 c0 = __ldg(p4+4), c1 = __ldg(p4+5), c2 = __ldg(p4+6), c3 = __ldg(p4+7);
        float delta = __ldg(g_xpp + (size_t)r*36 + 32);
        float dB[DS], Cc[DS];
        dB[0]=a0.x; dB[1]=a0.y; dB[2]=a0.z; dB[3]=a0.w;
        dB[4]=a1.x; dB[5]=a1.y; dB[6]=a1.z; dB[7]=a1.w;
        dB[8]=a2.x; dB[9]=a2.y; dB[10]=a2.z; dB[11]=a2.w;
        dB[12]=a3.x; dB[13]=a3.y; dB[14]=a3.z; dB[15]=a3.w;
        Cc[0]=c0.x; Cc[1]=c0.y; Cc[2]=c0.z; Cc[3]=c0.w;
        Cc[4]=c1.x; Cc[5]=c1.y; Cc[6]=c1.z; Cc[7]=c1.w;
        Cc[8]=c2.x; Cc[9]=c2.y; Cc[10]=c2.z; Cc[11]=c2.w;
        Cc[12]=c3.x; Cc[13]=c3.y; Cc[14]=c3.z; Cc[15]=c3.w;
        float xv = g_xc[(size_t)r*DI + d];
        float y  = Dd * xv;
        #pragma unroll
        for (int n=0;n<DS;n++) {
            float dA = __expf(delta * An[n]);
            h[n] = fmaf(dA, h[n], dB[n]*xv);
            y    = fmaf(h[n], Cc[n], y);
        }
        g_y[(size_t)r*DI + d] = y;
    }
    float* hf = g_hfin + ((size_t)(b*NC+c)*DI + d)*DS;
    #pragma unroll
    for (int n=0;n<DS;n++) hf[n] = h[n];
}

// ---------------- scan pass B: propagate chunk-entry states ----------------
__global__ void scanB_k(const float* __restrict__ logA, const float* __restrict__ init_state) {
    int idx = blockIdx.x*256 + threadIdx.x;    // BQ*DI*DS = 65536
    int n = idx & 15;
    int d = (idx >> 4) & (DI-1);
    int b = idx >> 15;
    float An = -__expf(logA[d*DS+n]);
    float h0 = init_state[idx];                // [b][d][n] layout matches idx
    #pragma unroll
    for (int c=0;c<NC;c++) {
        g_h0[((size_t)(b*NC+c)*DI + d)*DS + n] = h0;
        float P = __expf(An * g_S[b*NC+c]);
        h0 = fmaf(P, h0, g_hfin[((size_t)(b*NC+c)*DI + d)*DS + n]);
    }
}

// ---------------- scan pass C: decay the true entry state, add correction ----------------
__global__ void __launch_bounds__(256) scanC_k(const float* __restrict__ logA) {
    int d = blockIdx.x*256 + threadIdx.x;
    int b = blockIdx.y, c = blockIdx.z;
    float An[DS], hc[DS];
    const float* h0p = g_h0 + ((size_t)(b*NC+c)*DI + d)*DS;
    float ss = 0.f;
    #pragma unroll
    for (int n=0;n<DS;n++) {
        An[n] = -__expf(logA[d*DS+n]);
        hc[n] = h0p[n];
        ss += fabsf(hc[n]);
    }
    if (__all_sync(0xffffffffu, ss < 1e-30f)) return;
    int rbase = b*LQ + c*TCH;
    for (int t=0; t<TCH; t++) {
        int r = rbase + t;
        const float4* p4 = (const float4*)(g_xpp + (size_t)r*36);
        float4 c0 = __ldg(p4+4), c1 = __ldg(p4+5), c2 = __ldg(p4+6), c3 = __ldg(p4+7);
        float delta = __ldg(g_xpp + (size_t)r*36 + 32);
        float Cc[DS];
        Cc[0]=c0.x; Cc[1]=c0.y; Cc[2]=c0.z; Cc[3]=c0.w;
        Cc[4]=c1.x; Cc[5]=c1.y; Cc[6]=c1.z; Cc[7]=c1.w;
        Cc[8]=c2.x; Cc[9]=c2.y; Cc[10]=c2.z; Cc[11]=c2.w;
        Cc[12]=c3.x; Cc[13]=c3.y; Cc[14]=c3.z; Cc[15]=c3.w;
        float y = 0.f; ss = 0.f;
        #pragma unroll
        for (int n=0;n<DS;n++) {
            hc[n] *= __expf(delta * An[n]);
            y  = fmaf(hc[n], Cc[n], y);
            ss += fabsf(hc[n]);
        }
        g_y[(size_t)r*DI + d] += y;
        if (__all_sync(0xffffffffu, ss < 1e-28f)) break;   // states fully decayed
    }
}

// ---------------- gate: g = y * silu(z), bf16 ----------------
__global__ void gate_k() {
    int i = blockIdx.x*256 + threadIdx.x;
    if (i < NROW*DI) {
        int r = i >> 11, dc = i & (DI-1);
        float z  = g_xz[(size_t)r*(2*DI) + DI + dc];
        float sz = z / (1.f + __expf(-z));
        g_g[i] = __float2bfloat16(g_y[i] * sz);
    }
}

// ---------------- residual add ----------------
__global__ void resid_k(const float* __restrict__ x, float* __restrict__ out) {
    int i = blockIdx.x*256 + threadIdx.x;
    if (i < NROW*DM) out[i] = x[i] + g_ot[i];
}

// ---------------- launch ----------------
extern "C" void kernel_launch(void* const* d_in, const int* in_sizes, int n_in,
                              void* d_out, int out_size) {
    const float* x          = (const float*)d_in[0];
    const float* init_state = (const float*)d_in[1];
    const float* ln_w       = (const float*)d_in[2];
    const float* ln_b       = (const float*)d_in[3];
    const float* W_in       = (const float*)d_in[4];
    const float* conv_w     = (const float*)d_in[5];
    const float* conv_b     = (const float*)d_in[6];
    const float* W_x        = (const float*)d_in[7];
    const float* log_A      = (const float*)d_in[8];
    const float* D_param    = (const float*)d_in[9];
    const float* W_out      = (const float*)d_in[10];
    float* out = (float*)d_out;

    void *p_xn, *p_Win, *p_Wout, *p_Wx, *p_xz, *p_xcb, *p_xpraw, *p_g, *p_ot;
    cudaGetSymbolAddress(&p_xn,    g_xn);
    cudaGetSymbolAddress(&p_Win,   g_Win);
    cudaGetSymbolAddress(&p_Wout,  g_Wout);
    cudaGetSymbolAddress(&p_Wx,    g_Wx);
    cudaGetSymbolAddress(&p_xz,    g_xz);
    cudaGetSymbolAddress(&p_xcb,   g_xcb);
    cudaGetSymbolAddress(&p_xpraw, g_xpraw);
    cudaGetSymbolAddress(&p_g,     g_g);
    cudaGetSymbolAddress(&p_ot,    g_ot);

    cvt_win_k <<<(DM*2*DI+255)/256, 256>>>(W_in);
    cvt_wout_k<<<(DI*DM+255)/256,   256>>>(W_out);
    cvt_wx_k  <<<(DI*WXN+255)/256,  256>>>(W_x);

    ln_k<<<NROW, 256>>>(x, ln_w, ln_b);

    // GEMM1: xz[2048,4096] = xn[2048,1024] @ W_in[1024,4096]
    gemm_k<<<dim3(2*DI/BN, NROW/BM, 1), 256>>>((const __nv_bfloat16*)p_xn,
                                               (const __nv_bfloat16*)p_Win,
                                               (float*)p_xz, 2*DI, DM, DM, 0);

    conv_k<<<dim3(DI/256, NROW), 256>>>(conv_w, conv_b);

    // xp GEMM (split-K=8): partial[s][2048,128] = xcb[2048, s-slice] @ Wx[s-slice,128]
    gemm_k<<<dim3(WXN/BN, NROW/BM, KSPL), 256>>>((const __nv_bfloat16*)p_xcb,
                                                 (const __nv_bfloat16*)p_Wx,
                                                 (float*)p_xpraw, WXN, DI, DI/KSPL,
                                                 (size_t)NROW*WXN);

    xpost_k<<<NROW, 64>>>();
    sums_k<<<BQ*NC, TCH>>>();

    scanA_k<<<dim3(DI/256, BQ, NC), 256>>>(log_A, D_param);
    scanB_k<<<(BQ*DI*DS)/256, 256>>>(log_A, init_state);
    scanC_k<<<dim3(DI/256, BQ, NC), 256>>>(log_A);

    gate_k<<<(NROW*DI)/256, 256>>>();

    // GEMM2: ot[2048,1024] = g[2048,2048] @ W_out[2048,1024]
    gemm_k<<<dim3(DM/BN, NROW/BM, 1), 256>>>((const __nv_bfloat16*)p_g,
                                             (const __nv_bfloat16*)p_Wout,
                                             (float*)p_ot, DM, DI, DI, 0);

    resid_k<<<(NROW*DM)/256, 256>>>(x, out);
}

// round 5
// speedup vs baseline: 1.3520x; 1.1106x over previous
#include <cuda_runtime.h>
#include <cuda_bf16.h>
#include <mma.h>
#include <math.h>
#include <stdint.h>

using namespace nvcuda;

#define BQ   2
#define LQ   1024
#define DM   1024
#define DI   2048
#define DS   16
#define NROW (BQ*LQ)      // 2048
#define NC   8            // chunks
#define TCH  (LQ/NC)      // 128 steps per chunk
#define WXN  128          // padded N for the W_x gemm
#define KSPL 8            // split-K factor for xp gemm

// ---------------- scratch (__device__ globals; no allocs allowed) ----------------
__device__ __nv_bfloat16 g_xn[NROW*DM];            // layernorm out (bf16)
__device__ __nv_bfloat16 g_Win[DM*2*DI];           // W_in bf16
__device__ __nv_bfloat16 g_Wout[DI*DM];            // W_out bf16
__device__ __nv_bfloat16 g_Wx[DI*WXN];             // W_x bf16 padded to 128 cols
__device__ float         g_xz[(size_t)NROW*2*DI];  // gemm1 out: [:,0:2048]=x_ssm, [:,2048:]=z
__device__ float         g_xc[(size_t)NROW*DI];    // conv+silu out fp32
__device__ __nv_bfloat16 g_xcb[(size_t)NROW*DI];   // conv+silu out bf16
__device__ float         g_xpraw[(size_t)KSPL*NROW*WXN]; // xp gemm split-K partials
__device__ float         g_xpp[NROW*36];           // per (b,l): [0:16]=delta*B, [16:32]=C, [32]=delta
__device__ float         g_y[(size_t)NROW*DI];     // scan output
__device__ __nv_bfloat16 g_g[(size_t)NROW*DI];     // gated bf16 (gemm2 A)
__device__ float         g_ot[(size_t)NROW*DM];    // gemm2 out
__device__ float         g_hfin[BQ*NC*DI*DS];      // per-chunk local final states
__device__ float         g_h0[BQ*NC*DI*DS];        // true chunk-entry states
__device__ float         g_S[BQ*NC];               // per-chunk delta sums

// ---------------- fused weight converts ----------------
#define T1 (DM*2*DI)
#define T2 (DI*DM)
#define T3 (DI*WXN)
__global__ void cvt_all_k(const float* __restrict__ win,
                          const float* __restrict__ wout,
                          const float* __restrict__ wx) {
    int i = blockIdx.x*256 + threadIdx.x;
    if (i < T1) {
        g_Win[i] = __float2bfloat16(win[i]);
    } else if (i < T1+T2) {
        int j = i - T1;
        g_Wout[j] = __float2bfloat16(wout[j]);
    } else if (i < T1+T2+T3) {
        int j = i - T1 - T2;
        int k = j >> 7, n = j & (WXN-1);
        g_Wx[j] = __float2bfloat16(n < (2*DS+1) ? wx[k*(2*DS+1) + n] : 0.f);
    }
}

// ---------------- layernorm (block per row, bf16 out) ----------------
__global__ void ln_k(const float* __restrict__ x, const float* __restrict__ w,
                     const float* __restrict__ b) {
    __shared__ float red[8];
    __shared__ float bcast;
    int r = blockIdx.x, tid = threadIdx.x;
    const float* xr = x + (size_t)r*DM;
    float v0 = xr[tid], v1 = xr[tid+256], v2 = xr[tid+512], v3 = xr[tid+768];
    float s = v0+v1+v2+v3;
    #pragma unroll
    for (int o=16;o;o>>=1) s += __shfl_xor_sync(0xffffffffu, s, o);
    if ((tid&31)==0) red[tid>>5] = s;
    __syncthreads();
    if (tid==0) {
        float t = red[0]+red[1]+red[2]+red[3]+red[4]+red[5]+red[6]+red[7];
        bcast = t*(1.f/DM);
    }
    __syncthreads();
    float mu = bcast;
    float d0=v0-mu, d1=v1-mu, d2=v2-mu, d3=v3-mu;
    float q = d0*d0+d1*d1+d2*d2+d3*d3;
    __syncthreads();
    #pragma unroll
    for (int o=16;o;o>>=1) q += __shfl_xor_sync(0xffffffffu, q, o);
    if ((tid&31)==0) red[tid>>5] = q;
    __syncthreads();
    if (tid==0) {
        float t = red[0]+red[1]+red[2]+red[3]+red[4]+red[5]+red[6]+red[7];
        bcast = rsqrtf(t*(1.f/DM) + 1e-5f);
    }
    __syncthreads();
    float inv = bcast;
    __nv_bfloat16* o = g_xn + (size_t)r*DM;
    o[tid    ] = __float2bfloat16(d0*inv*w[tid    ] + b[tid    ]);
    o[tid+256] = __float2bfloat16(d1*inv*w[tid+256] + b[tid+256]);
    o[tid+512] = __float2bfloat16(d2*inv*w[tid+512] + b[tid+512]);
    o[tid+768] = __float2bfloat16(d3*inv*w[tid+768] + b[tid+768]);
}

// ---------------- pipelined bf16 wmma GEMM, 4 warps, 64x64 warp tiles ----------------
// C[M,N] = A[M,K-slice] @ B[K-slice,N]; slice = [bz*kchunk, (bz+1)*kchunk); C += bz*cstride
#define BM 128
#define BN 128
#define BK 32
#define APAD 16
#define BPAD 16

__device__ __forceinline__ void cpa16(void* dst_smem, const void* src_gmem) {
    unsigned d = (unsigned)__cvta_generic_to_shared(dst_smem);
    asm volatile("cp.async.cg.shared.global [%0], [%1], 16;" :: "r"(d), "l"(src_gmem));
}

__global__ void __launch_bounds__(128) gemm_k(const __nv_bfloat16* __restrict__ A,
                                              const __nv_bfloat16* __restrict__ B,
                                              float* __restrict__ C,
                                              int N, int K, int kchunk, size_t cstride) {
    __shared__ __align__(16) __nv_bfloat16 As[2][BM][BK+APAD];
    __shared__ __align__(16) __nv_bfloat16 Bs[2][BK][BN+BPAD];
    int bx = blockIdx.x, by = blockIdx.y, bz = blockIdx.z;
    int tid = threadIdx.x;
    int warp = tid >> 5;
    int wm = warp & 1;        // 2 warps in M (64 rows each)
    int wn = warp >> 1;       // 2 warps in N (64 cols each)
    int kbeg = bz * kchunk;
    C += (size_t)bz * cstride;

    wmma::fragment<wmma::accumulator,16,16,16,float> acc[4][4];
    #pragma unroll
    for (int i=0;i<4;i++)
        #pragma unroll
        for (int j=0;j<4;j++) wmma::fill_fragment(acc[i][j], 0.f);

    // per-thread copy coordinates (128 threads, 4 chunks each per tile)
    // A tile: 128 rows x 32 cols bf16 = 512 x 16B
    // B tile: 32 rows x 128 cols bf16 = 512 x 16B
    const __nv_bfloat16* Abase = A + (size_t)(by*BM)*K + kbeg;
    const __nv_bfloat16* Bbase = B + (size_t)kbeg*N + bx*BN;

    auto load_tile = [&](int s, int koff) {
        #pragma unroll
        for (int u=0; u<4; u++) {
            int idx = tid + u*128;
            int ar = idx >> 2, ac = idx & 3;
            cpa16(&As[s][ar][ac*8], Abase + (size_t)ar*K + koff + ac*8);
        }
        #pragma unroll
        for (int u=0; u<4; u++) {
            int idx = tid + u*128;
            int br = idx >> 4, bc = idx & 15;
            cpa16(&Bs[s][br][bc*8], Bbase + (size_t)(koff+br)*N + bc*8);
        }
        asm volatile("cp.async.commit_group;");
    };

    int ntiles = kchunk / BK;
    load_tile(0, 0);

    for (int it = 0; it < ntiles; it++) {
        if (it + 1 < ntiles) {
            load_tile((it+1)&1, (it+1)*BK);
            asm volatile("cp.async.wait_group 1;");
        } else {
            asm volatile("cp.async.wait_group 0;");
        }
        __syncthreads();
        int s = it & 1;
        #pragma unroll
        for (int kk=0; kk<BK; kk+=16) {
            wmma::fragment<wmma::matrix_a,16,16,16,__nv_bfloat16,wmma::row_major> af[4];
            wmma::fragment<wmma::matrix_b,16,16,16,__nv_bfloat16,wmma::row_major> bf[4];
            #pragma unroll
            for (int i=0;i<4;i++) wmma::load_matrix_sync(af[i], &As[s][wm*64+i*16][kk], BK+APAD);
            #pragma unroll
            for (int j=0;j<4;j++) wmma::load_matrix_sync(bf[j], &Bs[s][kk][wn*64+j*16], BN+BPAD);
            #pragma unroll
            for (int i=0;i<4;i++)
                #pragma unroll
                for (int j=0;j<4;j++) wmma::mma_sync(acc[i][j], af[i], bf[j], acc[i][j]);
        }
        __syncthreads();
    }

    #pragma unroll
    for (int i=0;i<4;i++)
        #pragma unroll
        for (int j=0;j<4;j++)
            wmma::store_matrix_sync(&C[(size_t)(by*BM+wm*64+i*16)*N + bx*BN+wn*64+j*16],
                                    acc[i][j], N, wmma::mem_row_major);
}

// ---------------- depthwise causal conv (k=4) + silu ----------------
__global__ void conv_k(const float* __restrict__ cw, const float* __restrict__ cb) {
    int d = blockIdx.x*256 + threadIdx.x;
    int r = blockIdx.y;
    int l = r & (LQ-1);
    float acc = cb[d];
    float w0 = cw[d*4+0], w1 = cw[d*4+1], w2 = cw[d*4+2], w3 = cw[d*4+3];
    const float* base = g_xz + (size_t)r*(2*DI) + d;
    if (l >= 3) acc = fmaf(base[-3*2*DI], w0, acc);
    if (l >= 2) acc = fmaf(base[-2*2*DI], w1, acc);
    if (l >= 1) acc = fmaf(base[-1*2*DI], w2, acc);
    acc = fmaf(base[0], w3, acc);
    float sv = acc / (1.f + __expf(-acc));
    g_xc[(size_t)r*DI + d]  = sv;
    g_xcb[(size_t)r*DI + d] = __float2bfloat16(sv);
}

// ---------------- xp postprocess: sum split-K partials, softplus(delta), fold delta into B ----------------
__global__ void xpost_k() {
    __shared__ float sd;
    int r = blockIdx.x, tid = threadIdx.x;
    float v = 0.f;
    if (tid < 33) {
        #pragma unroll
        for (int s=0; s<KSPL; s++)
            v += g_xpraw[(size_t)s*NROW*WXN + r*WXN + tid];
    }
    if (tid == 32) {
        float dl = (v > 20.f) ? v : log1pf(__expf(v));
        sd = dl;
        g_xpp[r*36 + 32] = dl;
    }
    __syncthreads();
    if (tid < 16)       g_xpp[r*36 + tid] = v * sd;   // delta * B_n
    else if (tid < 32)  g_xpp[r*36 + tid] = v;        // C_n
}

// ---------------- per-chunk delta sums ----------------
__global__ void sums_k() {
    __shared__ float red[4];
    int bc = blockIdx.x, t = threadIdx.x;      // 16 blocks x 128 threads
    int b = bc >> 3, c = bc & 7;
    float v = g_xpp[(size_t)((b*LQ + c*TCH + t))*36 + 32];
    #pragma unroll
    for (int o=16;o;o>>=1) v += __shfl_xor_sync(0xffffffffu, v, o);
    if ((t&31)==0) red[t>>5] = v;
    __syncthreads();
    if (t==0) g_S[bc] = red[0]+red[1]+red[2]+red[3];
}

// ---------------- scan pass A: local chunk scans, h_init = 0 ----------------
__global__ void __launch_bounds__(256) scanA_k(const float* __restrict__ logA,
                                               const float* __restrict__ Dp) {
    int d = blockIdx.x*256 + threadIdx.x;
    int b = blockIdx.y, c = blockIdx.z;
    float An[DS], h[DS];
    #pragma unroll
    for (int n=0;n<DS;n++) { An[n] = -__expf(logA[d*DS+n]); h[n] = 0.f; }
    float Dd = Dp[d];
    int rbase = b*LQ + c*TCH;
    for (int t=0; t<TCH; t++) {
        int r = rbase + t;
        const float4* p4 = (const float4*)(g_xpp + (size_t)r*36);
        float4 a0 = __ldg(p4+0), a1 = __ldg(p4+1), a2 = __ldg(p4+2), a3 = __ldg(p4+3);
        float4 c0 = __ldg(p4+4), c1 = __ldg(p4+5), c2 = __ldg(p4+6), c3 = __ldg(p4+7);
        float delta = __ldg(g_xpp + (size_t)r*36 + 32);
        float dB[DS], Cc[DS];
        dB[0]=a0.x; dB[1]=a0.y; dB[2]=a0.z; dB[3]=a0.w;
        dB[4]=a1.x; dB[5]=a1.y; dB[6]=a1.z; dB[7]=a1.w;
        dB[8]=a2.x; dB[9]=a2.y; dB[10]=a2.z; dB[11]=a2.w;
        dB[12]=a3.x; dB[13]=a3.y; dB[14]=a3.z; dB[15]=a3.w;
        Cc[0]=c0.x; Cc[1]=c0.y; Cc[2]=c0.z; Cc[3]=c0.w;
        Cc[4]=c1.x; Cc[5]=c1.y; Cc[6]=c1.z; Cc[7]=c1.w;
        Cc[8]=c2.x; Cc[9]=c2.y; Cc[10]=c2.z; Cc[11]=c2.w;
        Cc[12]=c3.x; Cc[13]=c3.y; Cc[14]=c3.z; Cc[15]=c3.w;
        float xv = g_xc[(size_t)r*DI + d];
        float y  = Dd * xv;
        #pragma unroll
        for (int n=0;n<DS;n++) {
            float dA = __expf(delta * An[n]);
            h[n] = fmaf(dA, h[n], dB[n]*xv);
            y    = fmaf(h[n], Cc[n], y);
        }
        g_y[(size_t)r*DI + d] = y;
    }
    float* hf = g_hfin + ((size_t)(b*NC+c)*DI + d)*DS;
    #pragma unroll
    for (int n=0;n<DS;n++) hf[n] = h[n];
}

// ---------------- scan pass B: propagate chunk-entry states ----------------
__global__ void scanB_k(const float* __restrict__ logA, const float* __restrict__ init_state) {
    int idx = blockIdx.x*256 + threadIdx.x;    // BQ*DI*DS = 65536
    int n = idx & 15;
    int d = (idx >> 4) & (DI-1);
    int b = idx >> 15;
    float An = -__expf(logA[d*DS+n]);
    float h0 = init_state[idx];                // [b][d][n] layout matches idx
    #pragma unroll
    for (int c=0;c<NC;c++) {
        g_h0[((size_t)(b*NC+c)*DI + d)*DS + n] = h0;
        float P = __expf(An * g_S[b*NC+c]);
        h0 = fmaf(P, h0, g_hfin[((size_t)(b*NC+c)*DI + d)*DS + n]);
    }
}

// ---------------- scan pass C: decay the true entry state, add correction ----------------
__global__ void __launch_bounds__(256) scanC_k(const float* __restrict__ logA) {
    int d = blockIdx.x*256 + threadIdx.x;
    int b = blockIdx.y, c = blockIdx.z;
    float An[DS], hc[DS];
    const float* h0p = g_h0 + ((size_t)(b*NC+c)*DI + d)*DS;
    float ss = 0.f;
    #pragma unroll
    for (int n=0;n<DS;n++) {
        An[n] = -__expf(logA[d*DS+n]);
        hc[n] = h0p[n];
        ss += fabsf(hc[n]);
    }
    if (__all_sync(0xffffffffu, ss < 1e-30f)) return;
    int rbase = b*LQ + c*TCH;
    for (int t=0; t<TCH; t++) {
        int r = rbase + t;
        const float4* p4 = (const float4*)(g_xpp + (size_t)r*36);
        float4 c0 = __ldg(p4+4), c1 = __ldg(p4+5), c2 = __ldg(p4+6), c3 = __ldg(p4+7);
        float delta = __ldg(g_xpp + (size_t)r*36 + 32);
        float Cc[DS];
        Cc[0]=c0.x; Cc[1]=c0.y; Cc[2]=c0.z; Cc[3]=c0.w;
        Cc[4]=c1.x; Cc[5]=c1.y; Cc[6]=c1.z; Cc[7]=c1.w;
        Cc[8]=c2.x; Cc[9]=c2.y; Cc[10]=c2.z; Cc[11]=c2.w;
        Cc[12]=c3.x; Cc[13]=c3.y; Cc[14]=c3.z; Cc[15]=c3.w;
        float y = 0.f; ss = 0.f;
        #pragma unroll
        for (int n=0;n<DS;n++) {
            hc[n] *= __expf(delta * An[n]);
            y  = fmaf(hc[n], Cc[n], y);
            ss += fabsf(hc[n]);
        }
        g_y[(size_t)r*DI + d] += y;
        if (__all_sync(0xffffffffu, ss < 1e-28f)) break;   // states fully decayed
    }
}

// ---------------- gate: g = y * silu(z), bf16 ----------------
__global__ void gate_k() {
    int i = blockIdx.x*256 + threadIdx.x;
    if (i < NROW*DI) {
        int r = i >> 11, dc = i & (DI-1);
        float z  = g_xz[(size_t)r*(2*DI) + DI + dc];
        float sz = z / (1.f + __expf(-z));
        g_g[i] = __float2bfloat16(g_y[i] * sz);
    }
}

// ---------------- residual add ----------------
__global__ void resid_k(const float* __restrict__ x, float* __restrict__ out) {
    int i = blockIdx.x*256 + threadIdx.x;
    if (i < NROW*DM) out[i] = x[i] + g_ot[i];
}

// ---------------- launch ----------------
extern "C" void kernel_launch(void* const* d_in, const int* in_sizes, int n_in,
                              void* d_out, int out_size) {
    const float* x          = (const float*)d_in[0];
    const float* init_state = (const float*)d_in[1];
    const float* ln_w       = (const float*)d_in[2];
    const float* ln_b       = (const float*)d_in[3];
    const float* W_in       = (const float*)d_in[4];
    const float* conv_w     = (const float*)d_in[5];
    const float* conv_b     = (const float*)d_in[6];
    const float* W_x        = (const float*)d_in[7];
    const float* log_A      = (const float*)d_in[8];
    const float* D_param    = (const float*)d_in[9];
    const float* W_out      = (const float*)d_in[10];
    float* out = (float*)d_out;

    void *p_xn, *p_Win, *p_Wout, *p_Wx, *p_xz, *p_xcb, *p_xpraw, *p_g, *p_ot;
    cudaGetSymbolAddress(&p_xn,    g_xn);
    cudaGetSymbolAddress(&p_Win,   g_Win);
    cudaGetSymbolAddress(&p_Wout,  g_Wout);
    cudaGetSymbolAddress(&p_Wx,    g_Wx);
    cudaGetSymbolAddress(&p_xz,    g_xz);
    cudaGetSymbolAddress(&p_xcb,   g_xcb);
    cudaGetSymbolAddress(&p_xpraw, g_xpraw);
    cudaGetSymbolAddress(&p_g,     g_g);
    cudaGetSymbolAddress(&p_ot,    g_ot);

    cvt_all_k<<<(T1+T2+T3+255)/256, 256>>>(W_in, W_out, W_x);

    ln_k<<<NROW, 256>>>(x, ln_w, ln_b);

    // GEMM1: xz[2048,4096] = xn[2048,1024] @ W_in[1024,4096]
    gemm_k<<<dim3(2*DI/BN, NROW/BM, 1), 128>>>((const __nv_bfloat16*)p_xn,
                                               (const __nv_bfloat16*)p_Win,
                                               (float*)p_xz, 2*DI, DM, DM, 0);

    conv_k<<<dim3(DI/256, NROW), 256>>>(conv_w, conv_b);

    // xp GEMM (split-K=8): partial[s][2048,128] = xcb[2048, s-slice] @ Wx[s-slice,128]
    gemm_k<<<dim3(WXN/BN, NROW/BM, KSPL), 128>>>((const __nv_bfloat16*)p_xcb,
                                                 (const __nv_bfloat16*)p_Wx,
                                                 (float*)p_xpraw, WXN, DI, DI/KSPL,
                                                 (size_t)NROW*WXN);

    xpost_k<<<NROW, 64>>>();
    sums_k<<<BQ*NC, TCH>>>();

    scanA_k<<<dim3(DI/256, BQ, NC), 256>>>(log_A, D_param);
    scanB_k<<<(BQ*DI*DS)/256, 256>>>(log_A, init_state);
    scanC_k<<<dim3(DI/256, BQ, NC), 256>>>(log_A);

    gate_k<<<(NROW*DI)/256, 256>>>();

    // GEMM2: ot[2048,1024] = g[2048,2048] @ W_out[2048,1024]
    gemm_k<<<dim3(DM/BN, NROW/BM, 1), 128>>>((const __nv_bfloat16*)p_g,
                                             (const __nv_bfloat16*)p_Wout,
                                             (float*)p_ot, DM, DI, DI, 0);

    resid_k<<<(NROW*DM)/256, 256>>>(x, out);
}

// round 6
// speedup vs baseline: 1.5456x; 1.1432x over previous
#include <cuda_runtime.h>
#include <cuda_bf16.h>
#include <mma.h>
#include <math.h>
#include <stdint.h>

using namespace nvcuda;

#define BQ   2
#define LQ   1024
#define DM   1024
#define DI   2048
#define DS   16
#define NROW (BQ*LQ)      // 2048
#define NC   8            // chunks
#define TCH  (LQ/NC)      // 128 steps per chunk
#define WXN  128          // padded N for the W_x gemm
#define KSPL 8            // split-K factor for xp gemm

// ---------------- scratch (__device__ globals; no allocs allowed) ----------------
__device__ __nv_bfloat16 g_xn[NROW*DM];            // layernorm out (bf16)
__device__ __nv_bfloat16 g_Win[DM*2*DI];           // W_in bf16
__device__ __nv_bfloat16 g_Wout[DI*DM];            // W_out bf16
__device__ __nv_bfloat16 g_Wx[DI*WXN];             // W_x bf16 padded to 128 cols
__device__ float         g_xz[(size_t)NROW*2*DI];  // gemm1 out: [:,0:2048]=x_ssm, [:,2048:]=z
__device__ float         g_xc[(size_t)NROW*DI];    // conv+silu out fp32
__device__ __nv_bfloat16 g_xcb[(size_t)NROW*DI];   // conv+silu out bf16
__device__ float         g_xpraw[(size_t)KSPL*NROW*WXN]; // xp gemm split-K partials
__device__ float         g_xpp[NROW*36];           // [0:16]=delta*B, [16:32]=C, [32]=delta, [33]=exp(-delta)
__device__ float         g_y[(size_t)NROW*DI];     // scan output
__device__ __nv_bfloat16 g_g[(size_t)NROW*DI];     // gated bf16 (gemm2 A)
__device__ float         g_hfin[BQ*NC*DI*DS];      // per-chunk local final states
__device__ float         g_h0[BQ*NC*DI*DS];        // true chunk-entry states
__device__ float         g_S[BQ*NC];               // per-chunk delta sums

// ---------------- fused weight converts ----------------
#define T1 (DM*2*DI)
#define T2 (DI*DM)
#define T3 (DI*WXN)
__global__ void cvt_all_k(const float* __restrict__ win,
                          const float* __restrict__ wout,
                          const float* __restrict__ wx) {
    int i = blockIdx.x*256 + threadIdx.x;
    if (i < T1) {
        g_Win[i] = __float2bfloat16(win[i]);
    } else if (i < T1+T2) {
        int j = i - T1;
        g_Wout[j] = __float2bfloat16(wout[j]);
    } else if (i < T1+T2+T3) {
        int j = i - T1 - T2;
        int k = j >> 7, n = j & (WXN-1);
        g_Wx[j] = __float2bfloat16(n < (2*DS+1) ? wx[k*(2*DS+1) + n] : 0.f);
    }
}

// ---------------- layernorm (block per row, bf16 out) ----------------
__global__ void ln_k(const float* __restrict__ x, const float* __restrict__ w,
                     const float* __restrict__ b) {
    __shared__ float red[8];
    __shared__ float bcast;
    int r = blockIdx.x, tid = threadIdx.x;
    const float* xr = x + (size_t)r*DM;
    float v0 = xr[tid], v1 = xr[tid+256], v2 = xr[tid+512], v3 = xr[tid+768];
    float s = v0+v1+v2+v3;
    #pragma unroll
    for (int o=16;o;o>>=1) s += __shfl_xor_sync(0xffffffffu, s, o);
    if ((tid&31)==0) red[tid>>5] = s;
    __syncthreads();
    if (tid==0) {
        float t = red[0]+red[1]+red[2]+red[3]+red[4]+red[5]+red[6]+red[7];
        bcast = t*(1.f/DM);
    }
    __syncthreads();
    float mu = bcast;
    float d0=v0-mu, d1=v1-mu, d2=v2-mu, d3=v3-mu;
    float q = d0*d0+d1*d1+d2*d2+d3*d3;
    __syncthreads();
    #pragma unroll
    for (int o=16;o;o>>=1) q += __shfl_xor_sync(0xffffffffu, q, o);
    if ((tid&31)==0) red[tid>>5] = q;
    __syncthreads();
    if (tid==0) {
        float t = red[0]+red[1]+red[2]+red[3]+red[4]+red[5]+red[6]+red[7];
        bcast = rsqrtf(t*(1.f/DM) + 1e-5f);
    }
    __syncthreads();
    float inv = bcast;
    __nv_bfloat16* o = g_xn + (size_t)r*DM;
    o[tid    ] = __float2bfloat16(d0*inv*w[tid    ] + b[tid    ]);
    o[tid+256] = __float2bfloat16(d1*inv*w[tid+256] + b[tid+256]);
    o[tid+512] = __float2bfloat16(d2*inv*w[tid+512] + b[tid+512]);
    o[tid+768] = __float2bfloat16(d3*inv*w[tid+768] + b[tid+768]);
}

// ---------------- pipelined bf16 wmma GEMM, 4 warps, 64x64 warp tiles ----------------
// C[M,N] = Cinit + A[M,K-slice] @ B[K-slice,N]; slice = [bz*kchunk,...); C += bz*cstride
#define BM 128
#define BN 128
#define BK 32
#define APAD 16
#define BPAD 16

__device__ __forceinline__ void cpa16(void* dst_smem, const void* src_gmem) {
    unsigned d = (unsigned)__cvta_generic_to_shared(dst_smem);
    asm volatile("cp.async.cg.shared.global [%0], [%1], 16;" :: "r"(d), "l"(src_gmem));
}

__global__ void __launch_bounds__(128) gemm_k(const __nv_bfloat16* __restrict__ A,
                                              const __nv_bfloat16* __restrict__ B,
                                              float* __restrict__ C,
                                              const float* __restrict__ Cinit,
                                              int N, int K, int kchunk, size_t cstride) {
    __shared__ __align__(16) __nv_bfloat16 As[2][BM][BK+APAD];
    __shared__ __align__(16) __nv_bfloat16 Bs[2][BK][BN+BPAD];
    int bx = blockIdx.x, by = blockIdx.y, bz = blockIdx.z;
    int tid = threadIdx.x;
    int warp = tid >> 5;
    int wm = warp & 1;        // 2 warps in M (64 rows each)
    int wn = warp >> 1;       // 2 warps in N (64 cols each)
    int kbeg = bz * kchunk;
    C += (size_t)bz * cstride;

    wmma::fragment<wmma::accumulator,16,16,16,float> acc[4][4];
    if (Cinit) {
        #pragma unroll
        for (int i=0;i<4;i++)
            #pragma unroll
            for (int j=0;j<4;j++)
                wmma::load_matrix_sync(acc[i][j],
                    &Cinit[(size_t)(by*BM+wm*64+i*16)*N + bx*BN+wn*64+j*16],
                    N, wmma::mem_row_major);
    } else {
        #pragma unroll
        for (int i=0;i<4;i++)
            #pragma unroll
            for (int j=0;j<4;j++) wmma::fill_fragment(acc[i][j], 0.f);
    }

    const __nv_bfloat16* Abase = A + (size_t)(by*BM)*K + kbeg;
    const __nv_bfloat16* Bbase = B + (size_t)kbeg*N + bx*BN;

    auto load_tile = [&](int s, int koff) {
        #pragma unroll
        for (int u=0; u<4; u++) {
            int idx = tid + u*128;
            int ar = idx >> 2, ac = idx & 3;
            cpa16(&As[s][ar][ac*8], Abase + (size_t)ar*K + koff + ac*8);
        }
        #pragma unroll
        for (int u=0; u<4; u++) {
            int idx = tid + u*128;
            int br = idx >> 4, bc = idx & 15;
            cpa16(&Bs[s][br][bc*8], Bbase + (size_t)(koff+br)*N + bc*8);
        }
        asm volatile("cp.async.commit_group;");
    };

    int ntiles = kchunk / BK;
    load_tile(0, 0);

    for (int it = 0; it < ntiles; it++) {
        if (it + 1 < ntiles) {
            load_tile((it+1)&1, (it+1)*BK);
            asm volatile("cp.async.wait_group 1;");
        } else {
            asm volatile("cp.async.wait_group 0;");
        }
        __syncthreads();
        int s = it & 1;
        #pragma unroll
        for (int kk=0; kk<BK; kk+=16) {
            wmma::fragment<wmma::matrix_a,16,16,16,__nv_bfloat16,wmma::row_major> af[4];
            wmma::fragment<wmma::matrix_b,16,16,16,__nv_bfloat16,wmma::row_major> bf[4];
            #pragma unroll
            for (int i=0;i<4;i++) wmma::load_matrix_sync(af[i], &As[s][wm*64+i*16][kk], BK+APAD);
            #pragma unroll
            for (int j=0;j<4;j++) wmma::load_matrix_sync(bf[j], &Bs[s][kk][wn*64+j*16], BN+BPAD);
            #pragma unroll
            for (int i=0;i<4;i++)
                #pragma unroll
                for (int j=0;j<4;j++) wmma::mma_sync(acc[i][j], af[i], bf[j], acc[i][j]);
        }
        __syncthreads();
    }

    #pragma unroll
    for (int i=0;i<4;i++)
        #pragma unroll
        for (int j=0;j<4;j++)
            wmma::store_matrix_sync(&C[(size_t)(by*BM+wm*64+i*16)*N + bx*BN+wn*64+j*16],
                                    acc[i][j], N, wmma::mem_row_major);
}

// ---------------- depthwise causal conv (k=4) + silu, 8 outputs/thread ----------------
#define CL 8
__global__ void conv_k(const float* __restrict__ cw, const float* __restrict__ cb) {
    int d  = blockIdx.x*256 + threadIdx.x;
    int r0 = blockIdx.y * CL;              // 8 consecutive rows, same batch
    int l0 = r0 & (LQ-1);
    float w0 = cw[d*4+0], w1 = cw[d*4+1], w2 = cw[d*4+2], w3 = cw[d*4+3];
    float bb = cb[d];
    float v[CL+3];
    #pragma unroll
    for (int i=0; i<CL+3; i++) {
        int l = l0 + i - 3;
        v[i] = (l >= 0) ? g_xz[(size_t)(r0 + i - 3)*(2*DI) + d] : 0.f;
    }
    #pragma unroll
    for (int j=0; j<CL; j++) {
        float acc = bb;
        acc = fmaf(v[j  ], w0, acc);
        acc = fmaf(v[j+1], w1, acc);
        acc = fmaf(v[j+2], w2, acc);
        acc = fmaf(v[j+3], w3, acc);
        float sv = acc / (1.f + __expf(-acc));
        g_xc[(size_t)(r0+j)*DI + d]  = sv;
        g_xcb[(size_t)(r0+j)*DI + d] = __float2bfloat16(sv);
    }
}

// ---------------- xp postprocess: sum split-K partials, softplus(delta), fold delta into B ----------------
__global__ void xpost_k() {
    __shared__ float sd;
    int r = blockIdx.x, tid = threadIdx.x;
    float v = 0.f;
    if (tid < 33) {
        #pragma unroll
        for (int s=0; s<KSPL; s++)
            v += g_xpraw[(size_t)s*NROW*WXN + r*WXN + tid];
    }
    if (tid == 32) {
        float dl = (v > 20.f) ? v : log1pf(__expf(v));
        sd = dl;
        g_xpp[r*36 + 32] = dl;
        g_xpp[r*36 + 33] = __expf(-dl);      // p = exp(-delta), for A_n = -(n+1) fast path
    }
    __syncthreads();
    if (tid < 16)       g_xpp[r*36 + tid] = v * sd;   // delta * B_n
    else if (tid < 32)  g_xpp[r*36 + tid] = v;        // C_n
}

// ---------------- per-chunk delta sums ----------------
__global__ void sums_k() {
    __shared__ float red[4];
    int bc = blockIdx.x, t = threadIdx.x;      // 16 blocks x 128 threads
    int b = bc >> 3, c = bc & 7;
    float v = g_xpp[(size_t)((b*LQ + c*TCH + t))*36 + 32];
    #pragma unroll
    for (int o=16;o;o>>=1) v += __shfl_xor_sync(0xffffffffu, v, o);
    if ((t&31)==0) red[t>>5] = v;
    __syncthreads();
    if (t==0) g_S[bc] = red[0]+red[1]+red[2]+red[3];
}

// detect A_n == -(n+1) (true for this model's log_A = log(1..16) tiled)
__device__ __forceinline__ bool an_is_seq(const float* An) {
    bool ok = true;
    #pragma unroll
    for (int n=0;n<DS;n++) ok &= (fabsf(An[n] + (float)(n+1)) < 1e-3f*(n+1));
    return ok;
}

// ---------------- scan pass A: local chunk scans, h_init = 0 ----------------
__global__ void __launch_bounds__(256) scanA_k(const float* __restrict__ logA,
                                               const float* __restrict__ Dp) {
    int d = blockIdx.x*256 + threadIdx.x;
    int b = blockIdx.y, c = blockIdx.z;
    float An[DS], h[DS];
    #pragma unroll
    for (int n=0;n<DS;n++) { An[n] = -__expf(logA[d*DS+n]); h[n] = 0.f; }
    bool fast = an_is_seq(An);
    float Dd = Dp[d];
    int rbase = b*LQ + c*TCH;
    for (int t=0; t<TCH; t++) {
        int r = rbase + t;
        const float4* p4 = (const float4*)(g_xpp + (size_t)r*36);
        float4 a0 = __ldg(p4+0), a1 = __ldg(p4+1), a2 = __ldg(p4+2), a3 = __ldg(p4+3);
        float4 c0 = __ldg(p4+4), c1 = __ldg(p4+5), c2 = __ldg(p4+6), c3 = __ldg(p4+7);
        float delta = __ldg(g_xpp + (size_t)r*36 + 32);
        float pw    = __ldg(g_xpp + (size_t)r*36 + 33);
        float dB[DS], Cc[DS];
        dB[0]=a0.x; dB[1]=a0.y; dB[2]=a0.z; dB[3]=a0.w;
        dB[4]=a1.x; dB[5]=a1.y; dB[6]=a1.z; dB[7]=a1.w;
        dB[8]=a2.x; dB[9]=a2.y; dB[10]=a2.z; dB[11]=a2.w;
        dB[12]=a3.x; dB[13]=a3.y; dB[14]=a3.z; dB[15]=a3.w;
        Cc[0]=c0.x; Cc[1]=c0.y; Cc[2]=c0.z; Cc[3]=c0.w;
        Cc[4]=c1.x; Cc[5]=c1.y; Cc[6]=c1.z; Cc[7]=c1.w;
        Cc[8]=c2.x; Cc[9]=c2.y; Cc[10]=c2.z; Cc[11]=c2.w;
        Cc[12]=c3.x; Cc[13]=c3.y; Cc[14]=c3.z; Cc[15]=c3.w;
        float xv = g_xc[(size_t)r*DI + d];
        float y  = Dd * xv;
        if (fast) {
            float pk = pw;                              // p^(n+1), n=0
            #pragma unroll
            for (int n=0;n<DS;n++) {
                h[n] = fmaf(pk, h[n], dB[n]*xv);
                y    = fmaf(h[n], Cc[n], y);
                pk  *= pw;
            }
        } else {
            #pragma unroll
            for (int n=0;n<DS;n++) {
                float dA = __expf(delta * An[n]);
                h[n] = fmaf(dA, h[n], dB[n]*xv);
                y    = fmaf(h[n], Cc[n], y);
            }
        }
        g_y[(size_t)r*DI + d] = y;
    }
    float* hf = g_hfin + ((size_t)(b*NC+c)*DI + d)*DS;
    #pragma unroll
    for (int n=0;n<DS;n++) hf[n] = h[n];
}

// ---------------- scan pass B: propagate chunk-entry states ----------------
__global__ void scanB_k(const float* __restrict__ logA, const float* __restrict__ init_state) {
    int idx = blockIdx.x*256 + threadIdx.x;    // BQ*DI*DS = 65536
    int n = idx & 15;
    int d = (idx >> 4) & (DI-1);
    int b = idx >> 15;
    float An = -__expf(logA[d*DS+n]);
    float h0 = init_state[idx];                // [b][d][n] layout matches idx
    #pragma unroll
    for (int c=0;c<NC;c++) {
        g_h0[((size_t)(b*NC+c)*DI + d)*DS + n] = h0;
        float P = __expf(An * g_S[b*NC+c]);
        h0 = fmaf(P, h0, g_hfin[((size_t)(b*NC+c)*DI + d)*DS + n]);
    }
}

// ---------------- scan pass C: decay the true entry state, add correction ----------------
__global__ void __launch_bounds__(256) scanC_k(const float* __restrict__ logA) {
    int d = blockIdx.x*256 + threadIdx.x;
    int b = blockIdx.y, c = blockIdx.z;
    float An[DS], hc[DS];
    const float* h0p = g_h0 + ((size_t)(b*NC+c)*DI + d)*DS;
    float ss = 0.f;
    #pragma unroll
    for (int n=0;n<DS;n++) {
        An[n] = -__expf(logA[d*DS+n]);
        hc[n] = h0p[n];
        ss += fabsf(hc[n]);
    }
    bool fast = an_is_seq(An);
    if (__all_sync(0xffffffffu, ss < 1e-30f)) return;
    int rbase = b*LQ + c*TCH;
    for (int t=0; t<TCH; t++) {
        int r = rbase + t;
        const float4* p4 = (const float4*)(g_xpp + (size_t)r*36);
        float4 c0 = __ldg(p4+4), c1 = __ldg(p4+5), c2 = __ldg(p4+6), c3 = __ldg(p4+7);
        float delta = __ldg(g_xpp + (size_t)r*36 + 32);
        float pw    = __ldg(g_xpp + (size_t)r*36 + 33);
        float Cc[DS];
        Cc[0]=c0.x; Cc[1]=c0.y; Cc[2]=c0.z; Cc[3]=c0.w;
        Cc[4]=c1.x; Cc[5]=c1.y; Cc[6]=c1.z; Cc[7]=c1.w;
        Cc[8]=c2.x; Cc[9]=c2.y; Cc[10]=c2.z; Cc[11]=c2.w;
        Cc[12]=c3.x; Cc[13]=c3.y; Cc[14]=c3.z; Cc[15]=c3.w;
        float y = 0.f; ss = 0.f;
        if (fast) {
            float pk = pw;
            #pragma unroll
            for (int n=0;n<DS;n++) {
                hc[n] *= pk;
                y  = fmaf(hc[n], Cc[n], y);
                ss += fabsf(hc[n]);
                pk *= pw;
            }
        } else {
            #pragma unroll
            for (int n=0;n<DS;n++) {
                hc[n] *= __expf(delta * An[n]);
                y  = fmaf(hc[n], Cc[n], y);
                ss += fabsf(hc[n]);
            }
        }
        g_y[(size_t)r*DI + d] += y;
        if (__all_sync(0xffffffffu, ss < 1e-28f)) break;   // states fully decayed
    }
}

// ---------------- gate: g = y * silu(z), bf16 ----------------
__global__ void gate_k() {
    int i = blockIdx.x*256 + threadIdx.x;
    if (i < NROW*DI) {
        int r = i >> 11, dc = i & (DI-1);
        float z  = g_xz[(size_t)r*(2*DI) + DI + dc];
        float sz = z / (1.f + __expf(-z));
        g_g[i] = __float2bfloat16(g_y[i] * sz);
    }
}

// ---------------- launch ----------------
extern "C" void kernel_launch(void* const* d_in, const int* in_sizes, int n_in,
                              void* d_out, int out_size) {
    const float* x          = (const float*)d_in[0];
    const float* init_state = (const float*)d_in[1];
    const float* ln_w       = (const float*)d_in[2];
    const float* ln_b       = (const float*)d_in[3];
    const float* W_in       = (const float*)d_in[4];
    const float* conv_w     = (const float*)d_in[5];
    const float* conv_b     = (const float*)d_in[6];
    const float* W_x        = (const float*)d_in[7];
    const float* log_A      = (const float*)d_in[8];
    const float* D_param    = (const float*)d_in[9];
    const float* W_out      = (const float*)d_in[10];
    float* out = (float*)d_out;

    void *p_xn, *p_Win, *p_Wout, *p_Wx, *p_xz, *p_xcb, *p_xpraw, *p_g;
    cudaGetSymbolAddress(&p_xn,    g_xn);
    cudaGetSymbolAddress(&p_Win,   g_Win);
    cudaGetSymbolAddress(&p_Wout,  g_Wout);
    cudaGetSymbolAddress(&p_Wx,    g_Wx);
    cudaGetSymbolAddress(&p_xz,    g_xz);
    cudaGetSymbolAddress(&p_xcb,   g_xcb);
    cudaGetSymbolAddress(&p_xpraw, g_xpraw);
    cudaGetSymbolAddress(&p_g,     g_g);

    cvt_all_k<<<(T1+T2+T3+255)/256, 256>>>(W_in, W_out, W_x);

    ln_k<<<NROW, 256>>>(x, ln_w, ln_b);

    // GEMM1: xz[2048,4096] = xn[2048,1024] @ W_in[1024,4096]
    gemm_k<<<dim3(2*DI/BN, NROW/BM, 1), 128>>>((const __nv_bfloat16*)p_xn,
                                               (const __nv_bfloat16*)p_Win,
                                               (float*)p_xz, nullptr, 2*DI, DM, DM, 0);

    conv_k<<<dim3(DI/256, NROW/CL), 256>>>(conv_w, conv_b);

    // xp GEMM (split-K=8)
    gemm_k<<<dim3(WXN/BN, NROW/BM, KSPL), 128>>>((const __nv_bfloat16*)p_xcb,
                                                 (const __nv_bfloat16*)p_Wx,
                                                 (float*)p_xpraw, nullptr, WXN, DI, DI/KSPL,
                                                 (size_t)NROW*WXN);

    xpost_k<<<NROW, 64>>>();
    sums_k<<<BQ*NC, TCH>>>();

    scanA_k<<<dim3(DI/256, BQ, NC), 256>>>(log_A, D_param);
    scanB_k<<<(BQ*DI*DS)/256, 256>>>(log_A, init_state);
    scanC_k<<<dim3(DI/256, BQ, NC), 256>>>(log_A);

    gate_k<<<(NROW*DI)/256, 256>>>();

    // GEMM2 (+fused residual): out = x + g[2048,2048] @ W_out[2048,1024]
    gemm_k<<<dim3(DM/BN, NROW/BM, 1), 128>>>((const __nv_bfloat16*)p_g,
                                             (const __nv_bfloat16*)p_Wout,
                                             out, x, DM, DI, DI, 0);
}

// round 8
// speedup vs baseline: 1.5545x; 1.0057x over previous
#include <cuda_runtime.h>
#include <cuda_bf16.h>
#include <mma.h>
#include <math.h>
#include <stdint.h>

using namespace nvcuda;

#define BQ   2
#define LQ   1024
#define DM   1024
#define DI   2048
#define DS   16
#define NROW (BQ*LQ)      // 2048
#define NC   8            // chunks
#define TCH  (LQ/NC)      // 128 steps per chunk
#define WXN  128          // padded N for the W_x gemm
#define KSPL 8            // split-K factor for xp gemm

// ---------------- scratch (__device__ globals; no allocs allowed) ----------------
__device__ __nv_bfloat16 g_xn[NROW*DM];            // layernorm out (bf16)
__device__ __nv_bfloat16 g_Win[DM*2*DI];           // W_in bf16
__device__ __nv_bfloat16 g_Wout[DI*DM];            // W_out bf16
__device__ __nv_bfloat16 g_Wx[DI*WXN];             // W_x bf16 padded to 128 cols
__device__ float         g_xz[(size_t)NROW*2*DI];  // gemm1 out
__device__ float         g_xc[(size_t)NROW*DI];    // conv+silu out fp32
__device__ __nv_bfloat16 g_xcb[(size_t)NROW*DI];   // conv+silu out bf16
__device__ float         g_xpraw[(size_t)KSPL*NROW*WXN];
__device__ float         g_xpp[NROW*36];           // [0:16]=delta*B, [16:32]=C, [32]=delta, [33]=exp(-delta)
__device__ float         g_y[(size_t)NROW*DI];
__device__ __nv_bfloat16 g_g[(size_t)NROW*DI];
__device__ float         g_hfin[BQ*NC*DI*DS];
__device__ float         g_h0[BQ*NC*DI*DS];
__device__ float         g_S[BQ*NC];

// ---------------- fused weight converts ----------------
#define T1 (DM*2*DI)
#define T2 (DI*DM)
#define T3 (DI*WXN)
__global__ void cvt_all_k(const float* __restrict__ win,
                          const float* __restrict__ wout,
                          const float* __restrict__ wx) {
    int i = blockIdx.x*256 + threadIdx.x;
    if (i < T1) {
        g_Win[i] = __float2bfloat16(win[i]);
    } else if (i < T1+T2) {
        int j = i - T1;
        g_Wout[j] = __float2bfloat16(wout[j]);
    } else if (i < T1+T2+T3) {
        int j = i - T1 - T2;
        int k = j >> 7, n = j & (WXN-1);
        g_Wx[j] = __float2bfloat16(n < (2*DS+1) ? wx[k*(2*DS+1) + n] : 0.f);
    }
}

// ---------------- layernorm (block per row, bf16 out) ----------------
__global__ void ln_k(const float* __restrict__ x, const float* __restrict__ w,
                     const float* __restrict__ b) {
    __shared__ float red[8];
    __shared__ float bcast;
    int r = blockIdx.x, tid = threadIdx.x;
    const float* xr = x + (size_t)r*DM;
    float v0 = xr[tid], v1 = xr[tid+256], v2 = xr[tid+512], v3 = xr[tid+768];
    float s = v0+v1+v2+v3;
    #pragma unroll
    for (int o=16;o;o>>=1) s += __shfl_xor_sync(0xffffffffu, s, o);
    if ((tid&31)==0) red[tid>>5] = s;
    __syncthreads();
    if (tid==0) {
        float t = red[0]+red[1]+red[2]+red[3]+red[4]+red[5]+red[6]+red[7];
        bcast = t*(1.f/DM);
    }
    __syncthreads();
    float mu = bcast;
    float d0=v0-mu, d1=v1-mu, d2=v2-mu, d3=v3-mu;
    float q = d0*d0+d1*d1+d2*d2+d3*d3;
    __syncthreads();
    #pragma unroll
    for (int o=16;o;o>>=1) q += __shfl_xor_sync(0xffffffffu, q, o);
    if ((tid&31)==0) red[tid>>5] = q;
    __syncthreads();
    if (tid==0) {
        float t = red[0]+red[1]+red[2]+red[3]+red[4]+red[5]+red[6]+red[7];
        bcast = rsqrtf(t*(1.f/DM) + 1e-5f);
    }
    __syncthreads();
    float inv = bcast;
    __nv_bfloat16* o = g_xn + (size_t)r*DM;
    o[tid    ] = __float2bfloat16(d0*inv*w[tid    ] + b[tid    ]);
    o[tid+256] = __float2bfloat16(d1*inv*w[tid+256] + b[tid+256]);
    o[tid+512] = __float2bfloat16(d2*inv*w[tid+512] + b[tid+512]);
    o[tid+768] = __float2bfloat16(d3*inv*w[tid+768] + b[tid+768]);
}

// ---------------- pipelined bf16 wmma GEMM, BK=64, dynamic smem ----------------
// C[M,N] = (Cinit +) A[M,K-slice] @ B[K-slice,N]; slice = [bz*kchunk,...); C += bz*cstride
#define BM 128
#define BN 128
#define BK 64
#define AP 8                       // pad (elems): A row = 72 elems (144B)
#define BP 16                      // pad (elems): B row = 144 elems (288B)
#define ASTR (BK+AP)               // 72
#define BSTR (BN+BP)               // 144
#define AST  (BM*ASTR)             // A stage elems 9216
#define BST  (BK*BSTR)             // B stage elems 9216
#define GSMEM ((2*AST + 2*BST) * 2)  // 73728 bytes

__device__ __forceinline__ void cpa16(void* dst_smem, const void* src_gmem) {
    unsigned d = (unsigned)__cvta_generic_to_shared(dst_smem);
    asm volatile("cp.async.cg.shared.global [%0], [%1], 16;" :: "r"(d), "l"(src_gmem));
}

__global__ void __launch_bounds__(128) gemm_k(const __nv_bfloat16* __restrict__ A,
                                              const __nv_bfloat16* __restrict__ B,
                                              float* __restrict__ C,
                                              const float* __restrict__ Cinit,
                                              int N, int K, int kchunk, size_t cstride) {
    extern __shared__ __nv_bfloat16 sm[];
    __nv_bfloat16* Asm = sm;               // [2][BM][ASTR]
    __nv_bfloat16* Bsm = sm + 2*AST;       // [2][BK][BSTR]
    int bx = blockIdx.x, by = blockIdx.y, bz = blockIdx.z;
    int tid = threadIdx.x;
    int warp = tid >> 5;
    int wm = warp & 1;        // 2 warps in M (64 rows each)
    int wn = warp >> 1;       // 2 warps in N (64 cols each)
    int kbeg = bz * kchunk;
    C += (size_t)bz * cstride;

    wmma::fragment<wmma::accumulator,16,16,16,float> acc[4][4];
    if (Cinit) {
        #pragma unroll
        for (int i=0;i<4;i++)
            #pragma unroll
            for (int j=0;j<4;j++)
                wmma::load_matrix_sync(acc[i][j],
                    &Cinit[(size_t)(by*BM+wm*64+i*16)*N + bx*BN+wn*64+j*16],
                    N, wmma::mem_row_major);
    } else {
        #pragma unroll
        for (int i=0;i<4;i++)
            #pragma unroll
            for (int j=0;j<4;j++) wmma::fill_fragment(acc[i][j], 0.f);
    }

    const __nv_bfloat16* Abase = A + (size_t)(by*BM)*K + kbeg;
    const __nv_bfloat16* Bbase = B + (size_t)kbeg*N + bx*BN;

    // A tile: 128 rows x 64 cols = 1024 x 16B chunks; B tile: 64 x 128 = 1024 chunks
    auto load_tile = [&](int s, int koff) {
        #pragma unroll
        for (int u=0; u<8; u++) {
            int idx = tid + u*128;
            int ar = idx >> 3, ac = idx & 7;
            cpa16(&Asm[s*AST + ar*ASTR + ac*8], Abase + (size_t)ar*K + koff + ac*8);
        }
        #pragma unroll
        for (int u=0; u<8; u++) {
            int idx = tid + u*128;
            int br = idx >> 4, bc = idx & 15;
            cpa16(&Bsm[s*BST + br*BSTR + bc*8], Bbase + (size_t)(koff+br)*N + bc*8);
        }
        asm volatile("cp.async.commit_group;");
    };

    int ntiles = kchunk / BK;
    load_tile(0, 0);

    for (int it = 0; it < ntiles; it++) {
        if (it + 1 < ntiles) {
            load_tile((it+1)&1, (it+1)*BK);
            asm volatile("cp.async.wait_group 1;");
        } else {
            asm volatile("cp.async.wait_group 0;");
        }
        __syncthreads();
        int s = it & 1;
        const __nv_bfloat16* Ap = &Asm[s*AST + wm*64*ASTR];
        const __nv_bfloat16* Bp = &Bsm[s*BST + wn*64];
        #pragma unroll
        for (int kk=0; kk<BK; kk+=16) {
            wmma::fragment<wmma::matrix_a,16,16,16,__nv_bfloat16,wmma::row_major> af[4];
            wmma::fragment<wmma::matrix_b,16,16,16,__nv_bfloat16,wmma::row_major> bf[4];
            #pragma unroll
            for (int i=0;i<4;i++) wmma::load_matrix_sync(af[i], Ap + i*16*ASTR + kk, ASTR);
            #pragma unroll
            for (int j=0;j<4;j++) wmma::load_matrix_sync(bf[j], Bp + kk*BSTR + j*16, BSTR);
            #pragma unroll
            for (int i=0;i<4;i++)
                #pragma unroll
                for (int j=0;j<4;j++) wmma::mma_sync(acc[i][j], af[i], bf[j], acc[i][j]);
        }
        __syncthreads();
    }

    #pragma unroll
    for (int i=0;i<4;i++)
        #pragma unroll
        for (int j=0;j<4;j++)
            wmma::store_matrix_sync(&C[(size_t)(by*BM+wm*64+i*16)*N + bx*BN+wn*64+j*16],
                                    acc[i][j], N, wmma::mem_row_major);
}

// ---------------- depthwise causal conv (k=4) + silu, 8 outputs/thread ----------------
#define CL 8
__global__ void conv_k(const float* __restrict__ cw, const float* __restrict__ cb) {
    int d  = blockIdx.x*256 + threadIdx.x;
    int r0 = blockIdx.y * CL;
    int l0 = r0 & (LQ-1);
    float w0 = cw[d*4+0], w1 = cw[d*4+1], w2 = cw[d*4+2], w3 = cw[d*4+3];
    float bb = cb[d];
    float v[CL+3];
    #pragma unroll
    for (int i=0; i<CL+3; i++) {
        int l = l0 + i - 3;
        v[i] = (l >= 0) ? g_xz[(size_t)(r0 + i - 3)*(2*DI) + d] : 0.f;
    }
    #pragma unroll
    for (int j=0; j<CL; j++) {
        float acc = bb;
        acc = fmaf(v[j  ], w0, acc);
        acc = fmaf(v[j+1], w1, acc);
        acc = fmaf(v[j+2], w2, acc);
        acc = fmaf(v[j+3], w3, acc);
        float sv = acc / (1.f + __expf(-acc));
        g_xc[(size_t)(r0+j)*DI + d]  = sv;
        g_xcb[(size_t)(r0+j)*DI + d] = __float2bfloat16(sv);
    }
}

// ---------------- xp postprocess ----------------
__global__ void xpost_k() {
    __shared__ float sd;
    int r = blockIdx.x, tid = threadIdx.x;
    float v = 0.f;
    if (tid < 33) {
        #pragma unroll
        for (int s=0; s<KSPL; s++)
            v += g_xpraw[(size_t)s*NROW*WXN + r*WXN + tid];
    }
    if (tid == 32) {
        float dl = (v > 20.f) ? v : log1pf(__expf(v));
        sd = dl;
        g_xpp[r*36 + 32] = dl;
        g_xpp[r*36 + 33] = __expf(-dl);
    }
    __syncthreads();
    if (tid < 16)       g_xpp[r*36 + tid] = v * sd;
    else if (tid < 32)  g_xpp[r*36 + tid] = v;
}

// ---------------- per-chunk delta sums ----------------
__global__ void sums_k() {
    __shared__ float red[4];
    int bc = blockIdx.x, t = threadIdx.x;
    int b = bc >> 3, c = bc & 7;
    float v = g_xpp[(size_t)((b*LQ + c*TCH + t))*36 + 32];
    #pragma unroll
    for (int o=16;o;o>>=1) v += __shfl_xor_sync(0xffffffffu, v, o);
    if ((t&31)==0) red[t>>5] = v;
    __syncthreads();
    if (t==0) g_S[bc] = red[0]+red[1]+red[2]+red[3];
}

__device__ __forceinline__ bool an_is_seq(const float* An) {
    bool ok = true;
    #pragma unroll
    for (int n=0;n<DS;n++) ok &= (fabsf(An[n] + (float)(n+1)) < 1e-3f*(n+1));
    return ok;
}

// ---------------- scan pass A ----------------
__global__ void __launch_bounds__(256) scanA_k(const float* __restrict__ logA,
                                               const float* __restrict__ Dp) {
    int d = blockIdx.x*256 + threadIdx.x;
    int b = blockIdx.y, c = blockIdx.z;
    float An[DS], h[DS];
    #pragma unroll
    for (int n=0;n<DS;n++) { An[n] = -__expf(logA[d*DS+n]); h[n] = 0.f; }
    bool fast = an_is_seq(An);
    float Dd = Dp[d];
    int rbase = b*LQ + c*TCH;
    for (int t=0; t<TCH; t++) {
        int r = rbase + t;
        const float4* p4 = (const float4*)(g_xpp + (size_t)r*36);
        float4 a0 = __ldg(p4+0), a1 = __ldg(p4+1), a2 = __ldg(p4+2), a3 = __ldg(p4+3);
        float4 c0 = __ldg(p4+4), c1 = __ldg(p4+5), c2 = __ldg(p4+6), c3 = __ldg(p4+7);
        float delta = __ldg(g_xpp + (size_t)r*36 + 32);
        float pw    = __ldg(g_xpp + (size_t)r*36 + 33);
        float dB[DS], Cc[DS];
        dB[0]=a0.x; dB[1]=a0.y; dB[2]=a0.z; dB[3]=a0.w;
        dB[4]=a1.x; dB[5]=a1.y; dB[6]=a1.z; dB[7]=a1.w;
        dB[8]=a2.x; dB[9]=a2.y; dB[10]=a2.z; dB[11]=a2.w;
        dB[12]=a3.x; dB[13]=a3.y; dB[14]=a3.z; dB[15]=a3.w;
        Cc[0]=c0.x; Cc[1]=c0.y; Cc[2]=c0.z; Cc[3]=c0.w;
        Cc[4]=c1.x; Cc[5]=c1.y; Cc[6]=c1.z; Cc[7]=c1.w;
        Cc[8]=c2.x; Cc[9]=c2.y; Cc[10]=c2.z; Cc[11]=c2.w;
        Cc[12]=c3.x; Cc[13]=c3.y; Cc[14]=c3.z; Cc[15]=c3.w;
        float xv = g_xc[(size_t)r*DI + d];
        float y  = Dd * xv;
        if (fast) {
            float pk = pw;
            #pragma unroll
            for (int n=0;n<DS;n++) {
                h[n] = fmaf(pk, h[n], dB[n]*xv);
                y    = fmaf(h[n], Cc[n], y);
                pk  *= pw;
            }
        } else {
            #pragma unroll
            for (int n=0;n<DS;n++) {
                float dA = __expf(delta * An[n]);
                h[n] = fmaf(dA, h[n], dB[n]*xv);
                y    = fmaf(h[n], Cc[n], y);
            }
        }
        g_y[(size_t)r*DI + d] = y;
    }
    float* hf = g_hfin + ((size_t)(b*NC+c)*DI + d)*DS;
    #pragma unroll
    for (int n=0;n<DS;n++) hf[n] = h[n];
}

// ---------------- scan pass B ----------------
__global__ void scanB_k(const float* __restrict__ logA, const float* __restrict__ init_state) {
    int idx = blockIdx.x*256 + threadIdx.x;
    int n = idx & 15;
    int d = (idx >> 4) & (DI-1);
    int b = idx >> 15;
    float An = -__expf(logA[d*DS+n]);
    float h0 = init_state[idx];
    #pragma unroll
    for (int c=0;c<NC;c++) {
        g_h0[((size_t)(b*NC+c)*DI + d)*DS + n] = h0;
        float P = __expf(An * g_S[b*NC+c]);
        h0 = fmaf(P, h0, g_hfin[((size_t)(b*NC+c)*DI + d)*DS + n]);
    }
}

// ---------------- scan pass C ----------------
__global__ void __launch_bounds__(256) scanC_k(const float* __restrict__ logA) {
    int d = blockIdx.x*256 + threadIdx.x;
    int b = blockIdx.y, c = blockIdx.z;
    float An[DS], hc[DS];
    const float* h0p = g_h0 + ((size_t)(b*NC+c)*DI + d)*DS;
    float ss = 0.f;
    #pragma unroll
    for (int n=0;n<DS;n++) {
        An[n] = -__expf(logA[d*DS+n]);
        hc[n] = h0p[n];
        ss += fabsf(hc[n]);
    }
    bool fast = an_is_seq(An);
    if (__all_sync(0xffffffffu, ss < 1e-30f)) return;
    int rbase = b*LQ + c*TCH;
    for (int t=0; t<TCH; t++) {
        int r = rbase + t;
        const float4* p4 = (const float4*)(g_xpp + (size_t)r*36);
        float4 c0 = __ldg(p4+4), c1 = __ldg(p4+5), c2 = __ldg(p4+6), c3 = __ldg(p4+7);
        float delta = __ldg(g_xpp + (size_t)r*36 + 32);
        float pw    = __ldg(g_xpp + (size_t)r*36 + 33);
        float Cc[DS];
        Cc[0]=c0.x; Cc[1]=c0.y; Cc[2]=c0.z; Cc[3]=c0.w;
        Cc[4]=c1.x; Cc[5]=c1.y; Cc[6]=c1.z; Cc[7]=c1.w;
        Cc[8]=c2.x; Cc[9]=c2.y; Cc[10]=c2.z; Cc[11]=c2.w;
        Cc[12]=c3.x; Cc[13]=c3.y; Cc[14]=c3.z; Cc[15]=c3.w;
        float y = 0.f; ss = 0.f;
        if (fast) {
            float pk = pw;
            #pragma unroll
            for (int n=0;n<DS;n++) {
                hc[n] *= pk;
                y  = fmaf(hc[n], Cc[n], y);
                ss += fabsf(hc[n]);
                pk *= pw;
            }
        } else {
            #pragma unroll
            for (int n=0;n<DS;n++) {
                hc[n] *= __expf(delta * An[n]);
                y  = fmaf(hc[n], Cc[n], y);
                ss += fabsf(hc[n]);
            }
        }
        g_y[(size_t)r*DI + d] += y;
        if (__all_sync(0xffffffffu, ss < 1e-28f)) break;
    }
}

// ---------------- gate ----------------
__global__ void gate_k() {
    int i = blockIdx.x*256 + threadIdx.x;
    if (i < NROW*DI) {
        int r = i >> 11, dc = i & (DI-1);
        float z  = g_xz[(size_t)r*(2*DI) + DI + dc];
        float sz = z / (1.f + __expf(-z));
        g_g[i] = __float2bfloat16(g_y[i] * sz);
    }
}

// ---------------- launch ----------------
extern "C" void kernel_launch(void* const* d_in, const int* in_sizes, int n_in,
                              void* d_out, int out_size) {
    const float* x          = (const float*)d_in[0];
    const float* init_state = (const float*)d_in[1];
    const float* ln_w       = (const float*)d_in[2];
    const float* ln_b       = (const float*)d_in[3];
    const float* W_in       = (const float*)d_in[4];
    const float* conv_w     = (const float*)d_in[5];
    const float* conv_b     = (const float*)d_in[6];
    const float* W_x        = (const float*)d_in[7];
    const float* log_A      = (const float*)d_in[8];
    const float* D_param    = (const float*)d_in[9];
    const float* W_out      = (const float*)d_in[10];
    float* out = (float*)d_out;

    void *p_xn, *p_Win, *p_Wout, *p_Wx, *p_xz, *p_xcb, *p_xpraw, *p_g;
    cudaGetSymbolAddress(&p_xn,    g_xn);
    cudaGetSymbolAddress(&p_Win,   g_Win);
    cudaGetSymbolAddress(&p_Wout,  g_Wout);
    cudaGetSymbolAddress(&p_Wx,    g_Wx);
    cudaGetSymbolAddress(&p_xz,    g_xz);
    cudaGetSymbolAddress(&p_xcb,   g_xcb);
    cudaGetSymbolAddress(&p_xpraw, g_xpraw);
    cudaGetSymbolAddress(&p_g,     g_g);

    static int smem_set = 0;
    if (!smem_set) {
        cudaFuncSetAttribute(gemm_k, cudaFuncAttributeMaxDynamicSharedMemorySize, GSMEM);
        smem_set = 1;
    }

    cvt_all_k<<<(T1+T2+T3+255)/256, 256>>>(W_in, W_out, W_x);

    ln_k<<<NROW, 256>>>(x, ln_w, ln_b);

    // GEMM1: xz[2048,4096] = xn[2048,1024] @ W_in[1024,4096]
    gemm_k<<<dim3(2*DI/BN, NROW/BM, 1), 128, GSMEM>>>((const __nv_bfloat16*)p_xn,
                                                      (const __nv_bfloat16*)p_Win,
                                                      (float*)p_xz, nullptr, 2*DI, DM, DM, 0);

    conv_k<<<dim3(DI/256, NROW/CL), 256>>>(conv_w, conv_b);

    // xp GEMM (split-K=8)
    gemm_k<<<dim3(WXN/BN, NROW/BM, KSPL), 128, GSMEM>>>((const __nv_bfloat16*)p_xcb,
                                                        (const __nv_bfloat16*)p_Wx,
                                                        (float*)p_xpraw, nullptr, WXN, DI, DI/KSPL,
                                                        (size_t)NROW*WXN);

    xpost_k<<<NROW, 64>>>();
    sums_k<<<BQ*NC, TCH>>>();

    scanA_k<<<dim3(DI/256, BQ, NC), 256>>>(log_A, D_param);
    scanB_k<<<(BQ*DI*DS)/256, 256>>>(log_A, init_state);
    scanC_k<<<dim3(DI/256, BQ, NC), 256>>>(log_A);

    gate_k<<<(NROW*DI)/256, 256>>>();

    // GEMM2 (+fused residual): out = x + g[2048,2048] @ W_out[2048,1024]
    gemm_k<<<dim3(DM/BN, NROW/BM, 1), 128, GSMEM>>>((const __nv_bfloat16*)p_g,
                                                    (const __nv_bfloat16*)p_Wout,
                                                    out, x, DM, DI, DI, 0);
}

// round 9
// speedup vs baseline: 1.6877x; 1.0857x over previous
#include <cuda_runtime.h>
#include <cuda_bf16.h>
#include <mma.h>
#include <math.h>
#include <stdint.h>

using namespace nvcuda;

#define BQ   2
#define LQ   1024
#define DM   1024
#define DI   2048
#define DS   16
#define NROW (BQ*LQ)      // 2048
#define NC   16           // chunks
#define TCH  (LQ/NC)      // 64 steps per chunk
#define WXN  128          // padded N for the W_x gemm
#define KSPL 8            // split-K factor for xp gemm

// ---------------- scratch ----------------
__device__ __nv_bfloat16 g_xn[NROW*DM];
__device__ __nv_bfloat16 g_Win[DM*2*DI];
__device__ __nv_bfloat16 g_Wout[DI*DM];
__device__ __nv_bfloat16 g_Wx[DI*WXN];
__device__ float         g_xz[(size_t)NROW*2*DI];
__device__ float         g_xc[(size_t)NROW*DI];
__device__ __nv_bfloat16 g_xcb[(size_t)NROW*DI];
__device__ float         g_xpraw[(size_t)KSPL*NROW*WXN];
__device__ float         g_xpp[NROW*36];           // [0:16]=delta*B, [16:32]=C, [32]=delta, [33]=exp(-delta)
__device__ __nv_bfloat16 g_g[(size_t)NROW*DI];     // gated output (gemm2 A)
__device__ float         g_hfin[BQ*NC*DI*DS];
__device__ float         g_h0[BQ*NC*DI*DS];
__device__ float         g_S[BQ*NC];

// ---------------- fused weight converts ----------------
#define T1 (DM*2*DI)
#define T2 (DI*DM)
#define T3 (DI*WXN)
__global__ void cvt_all_k(const float* __restrict__ win,
                          const float* __restrict__ wout,
                          const float* __restrict__ wx) {
    int i = blockIdx.x*256 + threadIdx.x;
    if (i < T1) {
        g_Win[i] = __float2bfloat16(win[i]);
    } else if (i < T1+T2) {
        int j = i - T1;
        g_Wout[j] = __float2bfloat16(wout[j]);
    } else if (i < T1+T2+T3) {
        int j = i - T1 - T2;
        int k = j >> 7, n = j & (WXN-1);
        g_Wx[j] = __float2bfloat16(n < (2*DS+1) ? wx[k*(2*DS+1) + n] : 0.f);
    }
}

// ---------------- layernorm ----------------
__global__ void ln_k(const float* __restrict__ x, const float* __restrict__ w,
                     const float* __restrict__ b) {
    __shared__ float red[8];
    __shared__ float bcast;
    int r = blockIdx.x, tid = threadIdx.x;
    const float* xr = x + (size_t)r*DM;
    float v0 = xr[tid], v1 = xr[tid+256], v2 = xr[tid+512], v3 = xr[tid+768];
    float s = v0+v1+v2+v3;
    #pragma unroll
    for (int o=16;o;o>>=1) s += __shfl_xor_sync(0xffffffffu, s, o);
    if ((tid&31)==0) red[tid>>5] = s;
    __syncthreads();
    if (tid==0) {
        float t = red[0]+red[1]+red[2]+red[3]+red[4]+red[5]+red[6]+red[7];
        bcast = t*(1.f/DM);
    }
    __syncthreads();
    float mu = bcast;
    float d0=v0-mu, d1=v1-mu, d2=v2-mu, d3=v3-mu;
    float q = d0*d0+d1*d1+d2*d2+d3*d3;
    __syncthreads();
    #pragma unroll
    for (int o=16;o;o>>=1) q += __shfl_xor_sync(0xffffffffu, q, o);
    if ((tid&31)==0) red[tid>>5] = q;
    __syncthreads();
    if (tid==0) {
        float t = red[0]+red[1]+red[2]+red[3]+red[4]+red[5]+red[6]+red[7];
        bcast = rsqrtf(t*(1.f/DM) + 1e-5f);
    }
    __syncthreads();
    float inv = bcast;
    __nv_bfloat16* o = g_xn + (size_t)r*DM;
    o[tid    ] = __float2bfloat16(d0*inv*w[tid    ] + b[tid    ]);
    o[tid+256] = __float2bfloat16(d1*inv*w[tid+256] + b[tid+256]);
    o[tid+512] = __float2bfloat16(d2*inv*w[tid+512] + b[tid+512]);
    o[tid+768] = __float2bfloat16(d3*inv*w[tid+768] + b[tid+768]);
}

// ---------------- pipelined bf16 wmma GEMM, BK=64, dynamic smem ----------------
#define BM 128
#define BN 128
#define BK 64
#define AP 8
#define BP 16
#define ASTR (BK+AP)
#define BSTR (BN+BP)
#define AST  (BM*ASTR)
#define BST  (BK*BSTR)
#define GSMEM ((2*AST + 2*BST) * 2)

__device__ __forceinline__ void cpa16(void* dst_smem, const void* src_gmem) {
    unsigned d = (unsigned)__cvta_generic_to_shared(dst_smem);
    asm volatile("cp.async.cg.shared.global [%0], [%1], 16;" :: "r"(d), "l"(src_gmem));
}

__global__ void __launch_bounds__(128) gemm_k(const __nv_bfloat16* __restrict__ A,
                                              const __nv_bfloat16* __restrict__ B,
                                              float* __restrict__ C,
                                              const float* __restrict__ Cinit,
                                              int N, int K, int kchunk, size_t cstride) {
    extern __shared__ __nv_bfloat16 sm[];
    __nv_bfloat16* Asm = sm;
    __nv_bfloat16* Bsm = sm + 2*AST;
    int bx = blockIdx.x, by = blockIdx.y, bz = blockIdx.z;
    int tid = threadIdx.x;
    int warp = tid >> 5;
    int wm = warp & 1;
    int wn = warp >> 1;
    int kbeg = bz * kchunk;
    C += (size_t)bz * cstride;

    wmma::fragment<wmma::accumulator,16,16,16,float> acc[4][4];
    if (Cinit) {
        #pragma unroll
        for (int i=0;i<4;i++)
            #pragma unroll
            for (int j=0;j<4;j++)
                wmma::load_matrix_sync(acc[i][j],
                    &Cinit[(size_t)(by*BM+wm*64+i*16)*N + bx*BN+wn*64+j*16],
                    N, wmma::mem_row_major);
    } else {
        #pragma unroll
        for (int i=0;i<4;i++)
            #pragma unroll
            for (int j=0;j<4;j++) wmma::fill_fragment(acc[i][j], 0.f);
    }

    const __nv_bfloat16* Abase = A + (size_t)(by*BM)*K + kbeg;
    const __nv_bfloat16* Bbase = B + (size_t)kbeg*N + bx*BN;

    auto load_tile = [&](int s, int koff) {
        #pragma unroll
        for (int u=0; u<8; u++) {
            int idx = tid + u*128;
            int ar = idx >> 3, ac = idx & 7;
            cpa16(&Asm[s*AST + ar*ASTR + ac*8], Abase + (size_t)ar*K + koff + ac*8);
        }
        #pragma unroll
        for (int u=0; u<8; u++) {
            int idx = tid + u*128;
            int br = idx >> 4, bc = idx & 15;
            cpa16(&Bsm[s*BST + br*BSTR + bc*8], Bbase + (size_t)(koff+br)*N + bc*8);
        }
        asm volatile("cp.async.commit_group;");
    };

    int ntiles = kchunk / BK;
    load_tile(0, 0);

    for (int it = 0; it < ntiles; it++) {
        if (it + 1 < ntiles) {
            load_tile((it+1)&1, (it+1)*BK);
            asm volatile("cp.async.wait_group 1;");
        } else {
            asm volatile("cp.async.wait_group 0;");
        }
        __syncthreads();
        int s = it & 1;
        const __nv_bfloat16* Ap = &Asm[s*AST + wm*64*ASTR];
        const __nv_bfloat16* Bp = &Bsm[s*BST + wn*64];
        #pragma unroll
        for (int kk=0; kk<BK; kk+=16) {
            wmma::fragment<wmma::matrix_a,16,16,16,__nv_bfloat16,wmma::row_major> af[4];
            wmma::fragment<wmma::matrix_b,16,16,16,__nv_bfloat16,wmma::row_major> bf[4];
            #pragma unroll
            for (int i=0;i<4;i++) wmma::load_matrix_sync(af[i], Ap + i*16*ASTR + kk, ASTR);
            #pragma unroll
            for (int j=0;j<4;j++) wmma::load_matrix_sync(bf[j], Bp + kk*BSTR + j*16, BSTR);
            #pragma unroll
            for (int i=0;i<4;i++)
                #pragma unroll
                for (int j=0;j<4;j++) wmma::mma_sync(acc[i][j], af[i], bf[j], acc[i][j]);
        }
        __syncthreads();
    }

    #pragma unroll
    for (int i=0;i<4;i++)
        #pragma unroll
        for (int j=0;j<4;j++)
            wmma::store_matrix_sync(&C[(size_t)(by*BM+wm*64+i*16)*N + bx*BN+wn*64+j*16],
                                    acc[i][j], N, wmma::mem_row_major);
}

// ---------------- depthwise causal conv (k=4) + silu ----------------
#define CL 8
__global__ void conv_k(const float* __restrict__ cw, const float* __restrict__ cb) {
    int d  = blockIdx.x*256 + threadIdx.x;
    int r0 = blockIdx.y * CL;
    int l0 = r0 & (LQ-1);
    float w0 = cw[d*4+0], w1 = cw[d*4+1], w2 = cw[d*4+2], w3 = cw[d*4+3];
    float bb = cb[d];
    float v[CL+3];
    #pragma unroll
    for (int i=0; i<CL+3; i++) {
        int l = l0 + i - 3;
        v[i] = (l >= 0) ? g_xz[(size_t)(r0 + i - 3)*(2*DI) + d] : 0.f;
    }
    #pragma unroll
    for (int j=0; j<CL; j++) {
        float acc = bb;
        acc = fmaf(v[j  ], w0, acc);
        acc = fmaf(v[j+1], w1, acc);
        acc = fmaf(v[j+2], w2, acc);
        acc = fmaf(v[j+3], w3, acc);
        float sv = acc / (1.f + __expf(-acc));
        g_xc[(size_t)(r0+j)*DI + d]  = sv;
        g_xcb[(size_t)(r0+j)*DI + d] = __float2bfloat16(sv);
    }
}

// ---------------- xp postprocess ----------------
__global__ void xpost_k() {
    __shared__ float sd;
    int r = blockIdx.x, tid = threadIdx.x;
    float v = 0.f;
    if (tid < 33) {
        #pragma unroll
        for (int s=0; s<KSPL; s++)
            v += g_xpraw[(size_t)s*NROW*WXN + r*WXN + tid];
    }
    if (tid == 32) {
        float dl = (v > 20.f) ? v : log1pf(__expf(v));
        sd = dl;
        g_xpp[r*36 + 32] = dl;
        g_xpp[r*36 + 33] = __expf(-dl);
    }
    __syncthreads();
    if (tid < 16)       g_xpp[r*36 + tid] = v * sd;
    else if (tid < 32)  g_xpp[r*36 + tid] = v;
}

// ---------------- per-chunk delta sums (TCH=64 -> 2 warps) ----------------
__global__ void sums_k() {
    __shared__ float red[2];
    int bc = blockIdx.x, t = threadIdx.x;      // BQ*NC blocks x TCH threads
    int b = bc / NC, c = bc % NC;
    float v = g_xpp[(size_t)((b*LQ + c*TCH + t))*36 + 32];
    #pragma unroll
    for (int o=16;o;o>>=1) v += __shfl_xor_sync(0xffffffffu, v, o);
    if ((t&31)==0) red[t>>5] = v;
    __syncthreads();
    if (t==0) g_S[bc] = red[0]+red[1];
}

__device__ __forceinline__ bool an_is_seq(const float* An) {
    bool ok = true;
    #pragma unroll
    for (int n=0;n<DS;n++) ok &= (fabsf(An[n] + (float)(n+1)) < 1e-3f*(n+1));
    return ok;
}

// row-data bundle for the scan, with manual prefetch
struct RowD { float4 a0,a1,a2,a3,c0,c1,c2,c3; float delta, pw, xv, zv; };
__device__ __forceinline__ void load_row(int r, int d, RowD& o) {
    const float4* p4 = (const float4*)(g_xpp + (size_t)r*36);
    o.a0 = __ldg(p4+0); o.a1 = __ldg(p4+1); o.a2 = __ldg(p4+2); o.a3 = __ldg(p4+3);
    o.c0 = __ldg(p4+4); o.c1 = __ldg(p4+5); o.c2 = __ldg(p4+6); o.c3 = __ldg(p4+7);
    o.delta = __ldg(g_xpp + (size_t)r*36 + 32);
    o.pw    = __ldg(g_xpp + (size_t)r*36 + 33);
    o.xv = __ldg(g_xc + (size_t)r*DI + d);
    o.zv = __ldg(g_xz + (size_t)r*(2*DI) + DI + d);
}

// ---------------- scan pass A: local chunk scans + fused gate ----------------
__global__ void __launch_bounds__(256) scanA_k(const float* __restrict__ logA,
                                               const float* __restrict__ Dp) {
    int d = blockIdx.x*256 + threadIdx.x;
    int b = blockIdx.y, c = blockIdx.z;
    float An[DS], h[DS];
    #pragma unroll
    for (int n=0;n<DS;n++) { An[n] = -__expf(logA[d*DS+n]); h[n] = 0.f; }
    bool fast = an_is_seq(An);
    float Dd = Dp[d];
    int rbase = b*LQ + c*TCH;

    RowD cur, nxt;
    load_row(rbase, d, cur);
    for (int t=0; t<TCH; t++) {
        int r = rbase + t;
        if (t+1 < TCH) load_row(r+1, d, nxt);     // prefetch overlaps compute below
        float dB[DS], Cc[DS];
        dB[0]=cur.a0.x; dB[1]=cur.a0.y; dB[2]=cur.a0.z; dB[3]=cur.a0.w;
        dB[4]=cur.a1.x; dB[5]=cur.a1.y; dB[6]=cur.a1.z; dB[7]=cur.a1.w;
        dB[8]=cur.a2.x; dB[9]=cur.a2.y; dB[10]=cur.a2.z; dB[11]=cur.a2.w;
        dB[12]=cur.a3.x; dB[13]=cur.a3.y; dB[14]=cur.a3.z; dB[15]=cur.a3.w;
        Cc[0]=cur.c0.x; Cc[1]=cur.c0.y; Cc[2]=cur.c0.z; Cc[3]=cur.c0.w;
        Cc[4]=cur.c1.x; Cc[5]=cur.c1.y; Cc[6]=cur.c1.z; Cc[7]=cur.c1.w;
        Cc[8]=cur.c2.x; Cc[9]=cur.c2.y; Cc[10]=cur.c2.z; Cc[11]=cur.c2.w;
        Cc[12]=cur.c3.x; Cc[13]=cur.c3.y; Cc[14]=cur.c3.z; Cc[15]=cur.c3.w;
        float xv = cur.xv;
        float y  = Dd * xv;
        if (fast) {
            float pk = cur.pw;
            #pragma unroll
            for (int n=0;n<DS;n++) {
                h[n] = fmaf(pk, h[n], dB[n]*xv);
                y    = fmaf(h[n], Cc[n], y);
                pk  *= cur.pw;
            }
        } else {
            #pragma unroll
            for (int n=0;n<DS;n++) {
                float dA = __expf(cur.delta * An[n]);
                h[n] = fmaf(dA, h[n], dB[n]*xv);
                y    = fmaf(h[n], Cc[n], y);
            }
        }
        float sz = cur.zv / (1.f + __expf(-cur.zv));
        g_g[(size_t)r*DI + d] = __float2bfloat16(y * sz);
        cur = nxt;
    }
    float* hf = g_hfin + ((size_t)(b*NC+c)*DI + d)*DS;
    #pragma unroll
    for (int n=0;n<DS;n++) hf[n] = h[n];
}

// ---------------- scan pass B: propagate chunk-entry states ----------------
__global__ void scanB_k(const float* __restrict__ logA, const float* __restrict__ init_state) {
    int idx = blockIdx.x*256 + threadIdx.x;    // BQ*DI*DS = 65536
    int n = idx & 15;
    int d = (idx >> 4) & (DI-1);
    int b = idx >> 15;
    float An = -__expf(logA[d*DS+n]);
    float h0 = init_state[idx];
    #pragma unroll
    for (int c=0;c<NC;c++) {
        g_h0[((size_t)(b*NC+c)*DI + d)*DS + n] = h0;
        float P = __expf(An * g_S[b*NC+c]);
        h0 = fmaf(P, h0, g_hfin[((size_t)(b*NC+c)*DI + d)*DS + n]);
    }
}

// ---------------- scan pass C: decay correction, RMW on gated output ----------------
__global__ void __launch_bounds__(256) scanC_k(const float* __restrict__ logA) {
    int d = blockIdx.x*256 + threadIdx.x;
    int b = blockIdx.y, c = blockIdx.z;
    float An[DS], hc[DS];
    const float* h0p = g_h0 + ((size_t)(b*NC+c)*DI + d)*DS;
    float ss = 0.f;
    #pragma unroll
    for (int n=0;n<DS;n++) {
        An[n] = -__expf(logA[d*DS+n]);
        hc[n] = h0p[n];
        ss += fabsf(hc[n]);
    }
    bool fast = an_is_seq(An);
    if (__all_sync(0xffffffffu, ss < 1e-30f)) return;
    int rbase = b*LQ + c*TCH;
    for (int t=0; t<TCH; t++) {
        int r = rbase + t;
        const float4* p4 = (const float4*)(g_xpp + (size_t)r*36);
        float4 c0 = __ldg(p4+4), c1 = __ldg(p4+5), c2 = __ldg(p4+6), c3 = __ldg(p4+7);
        float delta = __ldg(g_xpp + (size_t)r*36 + 32);
        float pw    = __ldg(g_xpp + (size_t)r*36 + 33);
        float Cc[DS];
        Cc[0]=c0.x; Cc[1]=c0.y; Cc[2]=c0.z; Cc[3]=c0.w;
        Cc[4]=c1.x; Cc[5]=c1.y; Cc[6]=c1.z; Cc[7]=c1.w;
        Cc[8]=c2.x; Cc[9]=c2.y; Cc[10]=c2.z; Cc[11]=c2.w;
        Cc[12]=c3.x; Cc[13]=c3.y; Cc[14]=c3.z; Cc[15]=c3.w;
        float y = 0.f; ss = 0.f;
        if (fast) {
            float pk = pw;
            #pragma unroll
            for (int n=0;n<DS;n++) {
                hc[n] *= pk;
                y  = fmaf(hc[n], Cc[n], y);
                ss += fabsf(hc[n]);
                pk *= pw;
            }
        } else {
            #pragma unroll
            for (int n=0;n<DS;n++) {
                hc[n] *= __expf(delta * An[n]);
                y  = fmaf(hc[n], Cc[n], y);
                ss += fabsf(hc[n]);
            }
        }
        float zv = __ldg(g_xz + (size_t)r*(2*DI) + DI + d);
        float sz = zv / (1.f + __expf(-zv));
        size_t gi = (size_t)r*DI + d;
        g_g[gi] = __float2bfloat16(__bfloat162float(g_g[gi]) + y * sz);
        if (__all_sync(0xffffffffu, ss < 1e-28f)) break;
    }
}

// ---------------- launch ----------------
extern "C" void kernel_launch(void* const* d_in, const int* in_sizes, int n_in,
                              void* d_out, int out_size) {
    const float* x          = (const float*)d_in[0];
    const float* init_state = (const float*)d_in[1];
    const float* ln_w       = (const float*)d_in[2];
    const float* ln_b       = (const float*)d_in[3];
    const float* W_in       = (const float*)d_in[4];
    const float* conv_w     = (const float*)d_in[5];
    const float* conv_b     = (const float*)d_in[6];
    const float* W_x        = (const float*)d_in[7];
    const float* log_A      = (const float*)d_in[8];
    const float* D_param    = (const float*)d_in[9];
    const float* W_out      = (const float*)d_in[10];
    float* out = (float*)d_out;

    void *p_xn, *p_Win, *p_Wout, *p_Wx, *p_xz, *p_xcb, *p_xpraw, *p_g;
    cudaGetSymbolAddress(&p_xn,    g_xn);
    cudaGetSymbolAddress(&p_Win,   g_Win);
    cudaGetSymbolAddress(&p_Wout,  g_Wout);
    cudaGetSymbolAddress(&p_Wx,    g_Wx);
    cudaGetSymbolAddress(&p_xz,    g_xz);
    cudaGetSymbolAddress(&p_xcb,   g_xcb);
    cudaGetSymbolAddress(&p_xpraw, g_xpraw);
    cudaGetSymbolAddress(&p_g,     g_g);

    static int smem_set = 0;
    if (!smem_set) {
        cudaFuncSetAttribute(gemm_k, cudaFuncAttributeMaxDynamicSharedMemorySize, GSMEM);
        smem_set = 1;
    }

    cvt_all_k<<<(T1+T2+T3+255)/256, 256>>>(W_in, W_out, W_x);

    ln_k<<<NROW, 256>>>(x, ln_w, ln_b);

    // GEMM1: xz[2048,4096] = xn[2048,1024] @ W_in[1024,4096]
    gemm_k<<<dim3(2*DI/BN, NROW/BM, 1), 128, GSMEM>>>((const __nv_bfloat16*)p_xn,
                                                      (const __nv_bfloat16*)p_Win,
                                                      (float*)p_xz, nullptr, 2*DI, DM, DM, 0);

    conv_k<<<dim3(DI/256, NROW/CL), 256>>>(conv_w, conv_b);

    // xp GEMM (split-K=8)
    gemm_k<<<dim3(WXN/BN, NROW/BM, KSPL), 128, GSMEM>>>((const __nv_bfloat16*)p_xcb,
                                                        (const __nv_bfloat16*)p_Wx,
                                                        (float*)p_xpraw, nullptr, WXN, DI, DI/KSPL,
                                                        (size_t)NROW*WXN);

    xpost_k<<<NROW, 64>>>();
    sums_k<<<BQ*NC, TCH>>>();

    scanA_k<<<dim3(DI/256, BQ, NC), 256>>>(log_A, D_param);
    scanB_k<<<(BQ*DI*DS)/256, 256>>>(log_A, init_state);
    scanC_k<<<dim3(DI/256, BQ, NC), 256>>>(log_A);

    // GEMM2 (+fused residual): out = x + g[2048,2048] @ W_out[2048,1024]
    gemm_k<<<dim3(DM/BN, NROW/BM, 1), 128, GSMEM>>>((const __nv_bfloat16*)p_g,
                                                    (const __nv_bfloat16*)p_Wout,
                                                    out, x, DM, DI, DI, 0);
}